// round 12
// baseline (speedup 1.0000x reference)
#include <cuda_runtime.h>
#include <cuda_bf16.h>
#include <math.h>
#include <stdint.h>

// ---------------------------------------------------------------------------
// Graphormer forward: B=32, N=512, D=256, H=8, DH=32, L=2
// GEMMs: mma.sync bf16 split-3-term, 128x256 CTA tile, 512 threads (16 warps,
//        warp tile 64x32), fused epilogues (colstats / relu / qkv / res+LN)
// Attention: FlashAttention-style register-level HMMA
// ---------------------------------------------------------------------------
#define B_   32
#define N_   512
#define D_   256
#define H_   8
#define DH_  32
#define L_   2
#define M_   (B_ * N_)
#define EPS_ 1e-5f

typedef unsigned long long u64;

// ---------------- scratch ----------------
__device__ float          g_h [M_ * D_];
__device__ float          g_t1[M_ * D_];
__device__ __nv_bfloat16  g_h0[M_ * D_];
__device__ __nv_bfloat16  g_h1[M_ * D_];
__device__ __nv_bfloat16  g_u0[M_ * D_];
__device__ __nv_bfloat16  g_u1[M_ * D_];
__device__ __nv_bfloat16  g_s0[M_ * 3 * D_];
__device__ __nv_bfloat16  g_s1[M_ * 3 * D_];
__device__ __nv_bfloat16  g_w0[917504];
__device__ __nv_bfloat16  g_w1[917504];
__device__ int            g_deg[M_];
__device__ float          g_sum[D_], g_sqsum[D_], g_scale[D_], g_shift[D_];

#define OFF_FIRST 0
#define OFF_QKV   65536
#define OFF_WO    458752
#define OFF_W1    589824
#define OFF_W2    720896
#define OFF_WIN   851968

// ---------------------------------------------------------------------------
// mma.sync / ldmatrix / cp.async helpers
// ---------------------------------------------------------------------------
__device__ __forceinline__ void mma_bf16(float* d, const uint32_t* a,
                                         const uint32_t* b) {
    asm volatile(
        "mma.sync.aligned.m16n8k16.row.col.f32.bf16.bf16.f32 "
        "{%0,%1,%2,%3}, {%4,%5,%6,%7}, {%8,%9}, {%0,%1,%2,%3};"
        : "+f"(d[0]), "+f"(d[1]), "+f"(d[2]), "+f"(d[3])
        : "r"(a[0]), "r"(a[1]), "r"(a[2]), "r"(a[3]), "r"(b[0]), "r"(b[1]));
}
__device__ __forceinline__ void ldmatrix_x4(uint32_t* r, const void* p) {
    uint32_t addr = (uint32_t)__cvta_generic_to_shared(p);
    asm volatile("ldmatrix.sync.aligned.m8n8.x4.shared.b16 {%0,%1,%2,%3}, [%4];"
                 : "=r"(r[0]), "=r"(r[1]), "=r"(r[2]), "=r"(r[3]) : "r"(addr));
}
__device__ __forceinline__ void ldmatrix_x2(uint32_t* r, const void* p) {
    uint32_t addr = (uint32_t)__cvta_generic_to_shared(p);
    asm volatile("ldmatrix.sync.aligned.m8n8.x2.shared.b16 {%0,%1}, [%2];"
                 : "=r"(r[0]), "=r"(r[1]) : "r"(addr));
}
__device__ __forceinline__ void cp16(void* smem, const void* gmem) {
    uint32_t s = (uint32_t)__cvta_generic_to_shared(smem);
    asm volatile("cp.async.cg.shared.global [%0], [%1], 16;"
                 :: "r"(s), "l"(gmem));
}
#define CP_COMMIT() asm volatile("cp.async.commit_group;" ::: "memory")
#define CP_WAIT1()  asm volatile("cp.async.wait_group 1;" ::: "memory")
#define CP_WAIT0()  asm volatile("cp.async.wait_group 0;" ::: "memory")

__device__ __forceinline__ uint32_t packbf(float a, float b) {
    __nv_bfloat162 h;
    h.x = __float2bfloat16(a);
    h.y = __float2bfloat16(b);
    return *(uint32_t*)&h;
}
__device__ __forceinline__ uint32_t packbf_lo(float a, float b, uint32_t hi) {
    __nv_bfloat162 h = *(__nv_bfloat162*)&hi;
    return packbf(a - __bfloat162float(h.x), b - __bfloat162float(h.y));
}

// ---------------------------------------------------------------------------
// bf16 split helpers
// ---------------------------------------------------------------------------
__device__ __forceinline__ void split_store(__nv_bfloat16* p0, __nv_bfloat16* p1,
                                            float v) {
    __nv_bfloat16 b0 = __float2bfloat16(v);
    *p0 = b0;
    *p1 = __float2bfloat16(v - __bfloat162float(b0));
}

__device__ __forceinline__ void split4(const float* src,
                                       __nv_bfloat16* d0,
                                       __nv_bfloat16* d1, int i) {
    float4 v = ((const float4*)src)[i];
    __nv_bfloat162 h0a, h0b, h1a, h1b;
    h0a.x = __float2bfloat16(v.x);
    h0a.y = __float2bfloat16(v.y);
    h0b.x = __float2bfloat16(v.z);
    h0b.y = __float2bfloat16(v.w);
    h1a.x = __float2bfloat16(v.x - __bfloat162float(h0a.x));
    h1a.y = __float2bfloat16(v.y - __bfloat162float(h0a.y));
    h1b.x = __float2bfloat16(v.z - __bfloat162float(h0b.x));
    h1b.y = __float2bfloat16(v.w - __bfloat162float(h0b.y));
    ((__nv_bfloat162*)d0)[i * 2 + 0] = h0a;
    ((__nv_bfloat162*)d0)[i * 2 + 1] = h0b;
    ((__nv_bfloat162*)d1)[i * 2 + 0] = h1a;
    ((__nv_bfloat162*)d1)[i * 2 + 1] = h1b;
}

__global__ void split_kernel(const float* __restrict__ src,
                             __nv_bfloat16* __restrict__ d0,
                             __nv_bfloat16* __restrict__ d1, int n4) {
    int i = blockIdx.x * 256 + threadIdx.x;
    if (i >= n4) return;
    split4(src, d0, d1, i);
}

__global__ void split5_kernel(const float* __restrict__ Wf,
                              const float* __restrict__ Wo,
                              const float* __restrict__ W1f,
                              const float* __restrict__ W2f,
                              const float* __restrict__ Win,
                              __nv_bfloat16* __restrict__ w0,
                              __nv_bfloat16* __restrict__ w1) {
    int b = blockIdx.x;
    if (b == 0) {
        g_sum[threadIdx.x] = 0.f;
        g_sqsum[threadIdx.x] = 0.f;
    }
    const float* src; int base, rel;
    if (b < 64)       { src = Wf;  base = OFF_FIRST; rel = b; }
    else if (b < 192) { src = Wo;  base = OFF_WO;    rel = b - 64; }
    else if (b < 320) { src = W1f; base = OFF_W1;    rel = b - 192; }
    else if (b < 448) { src = W2f; base = OFF_W2;    rel = b - 320; }
    else              { src = Win; base = OFF_WIN;   rel = b - 448; }
    int i = rel * 256 + threadIdx.x;
    split4(src, w0 + base, w1 + base, i);
}

// ---------------------------------------------------------------------------
// GEMM: 128x256 CTA tile, 512 threads (16 warps, 2x8), warp tile 64x32,
// BK=32, K=256, 2-stage cp.async. Epilogues:
//   EPI 0: fp32 out + fused column stats.  EPI 1: relu + bf16 splits.
//   EPI 2: bf16 splits (Q block scaled).   EPI 3: residual + LayerNorm.
// ---------------------------------------------------------------------------
#define PADK     40
#define A_TILE_B (128 * PADK * 2)
#define W_TILE_B (256 * PADK * 2)
#define STAGE_B  (2 * A_TILE_B + 2 * W_TILE_B)   // 61440
#define HDR_B    9216                             // bias 1K + psum 4K + psq 4K
#define GEMM_SMEM (HDR_B + 2 * STAGE_B)           // 132096

__device__ __forceinline__ void load_stage(
    char* buf, const __nv_bfloat16* A0, const __nv_bfloat16* A1,
    const __nv_bfloat16* W0, const __nv_bfloat16* W1,
    int bm, int bn, int k0, int tid)
{
    #pragma unroll
    for (int i = 0; i < 2; i++) {               // A tiles: 1024 chunks
        int id  = tid + i * 512;
        int s   = id >> 9;
        int row = (id >> 2) & 127;
        int cb  = id & 3;
        const __nv_bfloat16* src = s ? A1 : A0;
        cp16(buf + s * A_TILE_B + row * 80 + cb * 16,
             &src[(size_t)(bm + row) * 256 + k0 + cb * 8]);
    }
    char* wb = buf + 2 * A_TILE_B;
    #pragma unroll
    for (int i = 0; i < 4; i++) {               // W tiles: 2048 chunks
        int id  = tid + i * 512;
        int s   = id >> 10;
        int row = (id >> 2) & 255;
        int cb  = id & 3;
        const __nv_bfloat16* src = s ? W1 : W0;
        cp16(wb + s * W_TILE_B + row * 80 + cb * 16,
             &src[(size_t)(bn + row) * 256 + k0 + cb * 8]);
    }
}

template <int EPI>
__global__ __launch_bounds__(512, 1) void gemm_mma(
    const __nv_bfloat16* __restrict__ A0, const __nv_bfloat16* __restrict__ A1,
    const __nv_bfloat16* __restrict__ W0, const __nv_bfloat16* __restrict__ W1,
    const float* __restrict__ bias, float* __restrict__ Cf,
    __nv_bfloat16* __restrict__ U0, __nv_bfloat16* __restrict__ U1, int Nc,
    const float* __restrict__ gamma, const float* __restrict__ beta)
{
    extern __shared__ char smem[];
    float* bsm  = (float*)smem;                 // [256]
    float* psum = (float*)(smem + 1024);        // [128][8]
    float* psq  = (float*)(smem + 5120);        // [128][8]

    const int tid  = threadIdx.x;
    const int wid  = tid >> 5;
    const int lane = tid & 31;
    const int bm   = blockIdx.x * 128;
    const int bn   = blockIdx.y * 256;
    const int wm   = wid >> 3;                  // 0..1
    const int wn   = wid & 7;                   // 0..7

    if (tid < 256) bsm[tid] = bias[bn + tid];

    float acc[4][4][4];
    #pragma unroll
    for (int mi = 0; mi < 4; mi++)
        #pragma unroll
        for (int ni = 0; ni < 4; ni++)
            #pragma unroll
            for (int k = 0; k < 4; k++) acc[mi][ni][k] = 0.f;

    const int alr = lane & 15;
    const int alc = (lane >> 4) * 8;
    const int blr = lane & 7;
    const int blc = ((lane >> 3) & 1) * 8;

    load_stage(smem + HDR_B, A0, A1, W0, W1, bm, bn, 0, tid);
    CP_COMMIT();

    #pragma unroll
    for (int c = 0; c < 8; c++) {
        if (c < 7) {
            load_stage(smem + HDR_B + ((c + 1) & 1) * STAGE_B,
                       A0, A1, W0, W1, bm, bn, (c + 1) * 32, tid);
            CP_COMMIT();
            CP_WAIT1();
        } else {
            CP_WAIT0();
        }
        __syncthreads();

        char* buf = smem + HDR_B + (c & 1) * STAGE_B;
        __nv_bfloat16* A0s = (__nv_bfloat16*)(buf);
        __nv_bfloat16* A1s = (__nv_bfloat16*)(buf + A_TILE_B);
        __nv_bfloat16* W0s = (__nv_bfloat16*)(buf + 2 * A_TILE_B);
        __nv_bfloat16* W1s = (__nv_bfloat16*)(buf + 2 * A_TILE_B + W_TILE_B);

        #pragma unroll
        for (int ks = 0; ks < 32; ks += 16) {
            uint32_t af0[4][4], wf[4][2];
            // A0 x W0
            #pragma unroll
            for (int mi = 0; mi < 4; mi++)
                ldmatrix_x4(af0[mi],
                    &A0s[(wm * 64 + mi * 16 + alr) * PADK + ks + alc]);
            #pragma unroll
            for (int ni = 0; ni < 4; ni++)
                ldmatrix_x2(wf[ni],
                    &W0s[(wn * 32 + ni * 8 + blr) * PADK + ks + blc]);
            #pragma unroll
            for (int mi = 0; mi < 4; mi++)
                #pragma unroll
                for (int ni = 0; ni < 4; ni++)
                    mma_bf16(acc[mi][ni], af0[mi], wf[ni]);
            // A1 x W0 (A1 in fresh regs; W0 dies after)
            {
                uint32_t af1[4][4];
                #pragma unroll
                for (int mi = 0; mi < 4; mi++)
                    ldmatrix_x4(af1[mi],
                        &A1s[(wm * 64 + mi * 16 + alr) * PADK + ks + alc]);
                #pragma unroll
                for (int mi = 0; mi < 4; mi++)
                    #pragma unroll
                    for (int ni = 0; ni < 4; ni++)
                        mma_bf16(acc[mi][ni], af1[mi], wf[ni]);
            }
            // A0 x W1 (reuse wf regs)
            #pragma unroll
            for (int ni = 0; ni < 4; ni++)
                ldmatrix_x2(wf[ni],
                    &W1s[(wn * 32 + ni * 8 + blr) * PADK + ks + blc]);
            #pragma unroll
            for (int mi = 0; mi < 4; mi++)
                #pragma unroll
                for (int ni = 0; ni < 4; ni++)
                    mma_bf16(acc[mi][ni], af0[mi], wf[ni]);
        }
        __syncthreads();
    }

    const int qr  = lane >> 2;
    const int qc2 = (lane & 3) * 2;

    if (EPI == 0) {
        #pragma unroll
        for (int ni = 0; ni < 4; ni++) {
            const int cl = wn * 32 + ni * 8 + qc2;
            const int gc = bn + cl;
            float cs0 = 0.f, cs1 = 0.f, cq0 = 0.f, cq1 = 0.f;
            #pragma unroll
            for (int mi = 0; mi < 4; mi++) {
                const int r0 = bm + wm * 64 + mi * 16 + qr;
                float v00 = acc[mi][ni][0] + bsm[cl];
                float v01 = acc[mi][ni][1] + bsm[cl + 1];
                float v10 = acc[mi][ni][2] + bsm[cl];
                float v11 = acc[mi][ni][3] + bsm[cl + 1];
                *(float2*)&Cf[(size_t)r0 * Nc + gc]       = make_float2(v00, v01);
                *(float2*)&Cf[(size_t)(r0 + 8) * Nc + gc] = make_float2(v10, v11);
                cs0 += v00 + v10; cs1 += v01 + v11;
                cq0 += v00 * v00 + v10 * v10;
                cq1 += v01 * v01 + v11 * v11;
            }
            #pragma unroll
            for (int off = 4; off <= 16; off <<= 1) {
                cs0 += __shfl_xor_sync(0xffffffffu, cs0, off);
                cs1 += __shfl_xor_sync(0xffffffffu, cs1, off);
                cq0 += __shfl_xor_sync(0xffffffffu, cq0, off);
                cq1 += __shfl_xor_sync(0xffffffffu, cq1, off);
            }
            if (qr == 0) {
                atomicAdd(&g_sum[gc],       cs0);
                atomicAdd(&g_sum[gc + 1],   cs1);
                atomicAdd(&g_sqsum[gc],     cq0);
                atomicAdd(&g_sqsum[gc + 1], cq1);
            }
        }
    } else if (EPI == 1 || EPI == 2) {
        const float esc = (EPI == 2 && blockIdx.y == 0) ? 0.17677669529663687f
                                                        : 1.0f;
        #pragma unroll
        for (int mi = 0; mi < 4; mi++) {
            #pragma unroll
            for (int ni = 0; ni < 4; ni++) {
                const int cl = wn * 32 + ni * 8 + qc2;
                const int gc = bn + cl;
                const int r0 = bm + wm * 64 + mi * 16 + qr;
                float v00 = acc[mi][ni][0] + bsm[cl];
                float v01 = acc[mi][ni][1] + bsm[cl + 1];
                float v10 = acc[mi][ni][2] + bsm[cl];
                float v11 = acc[mi][ni][3] + bsm[cl + 1];
                if (EPI == 1) {
                    v00 = fmaxf(v00, 0.f); v01 = fmaxf(v01, 0.f);
                    v10 = fmaxf(v10, 0.f); v11 = fmaxf(v11, 0.f);
                } else {
                    v00 *= esc; v01 *= esc; v10 *= esc; v11 *= esc;
                }
                uint32_t hi0 = packbf(v00, v01);
                uint32_t lo0 = packbf_lo(v00, v01, hi0);
                uint32_t hi1 = packbf(v10, v11);
                uint32_t lo1 = packbf_lo(v10, v11, hi1);
                *(uint32_t*)&U0[(size_t)r0 * Nc + gc]       = hi0;
                *(uint32_t*)&U1[(size_t)r0 * Nc + gc]       = lo0;
                *(uint32_t*)&U0[(size_t)(r0 + 8) * Nc + gc] = hi1;
                *(uint32_t*)&U1[(size_t)(r0 + 8) * Nc + gc] = lo1;
            }
        }
    } else {
        // EPI 3: y = acc + bias + residual(Cf); LayerNorm(y); write h/h0/h1
        #pragma unroll
        for (int mi = 0; mi < 4; mi++) {
            const int lr0 = wm * 64 + mi * 16 + qr;
            const int gr0 = bm + lr0;
            float sA = 0.f, qA = 0.f, sB = 0.f, qB = 0.f;
            #pragma unroll
            for (int ni = 0; ni < 4; ni++) {
                const int cl = wn * 32 + ni * 8 + qc2;
                float2 h0v = *(float2*)&Cf[(size_t)gr0 * 256 + cl];
                float2 h1v = *(float2*)&Cf[(size_t)(gr0 + 8) * 256 + cl];
                float v00 = acc[mi][ni][0] + bsm[cl]     + h0v.x;
                float v01 = acc[mi][ni][1] + bsm[cl + 1] + h0v.y;
                float v10 = acc[mi][ni][2] + bsm[cl]     + h1v.x;
                float v11 = acc[mi][ni][3] + bsm[cl + 1] + h1v.y;
                acc[mi][ni][0] = v00; acc[mi][ni][1] = v01;
                acc[mi][ni][2] = v10; acc[mi][ni][3] = v11;
                sA += v00 + v01; qA += v00 * v00 + v01 * v01;
                sB += v10 + v11; qB += v10 * v10 + v11 * v11;
            }
            sA += __shfl_xor_sync(0xffffffffu, sA, 1);
            sA += __shfl_xor_sync(0xffffffffu, sA, 2);
            qA += __shfl_xor_sync(0xffffffffu, qA, 1);
            qA += __shfl_xor_sync(0xffffffffu, qA, 2);
            sB += __shfl_xor_sync(0xffffffffu, sB, 1);
            sB += __shfl_xor_sync(0xffffffffu, sB, 2);
            qB += __shfl_xor_sync(0xffffffffu, qB, 1);
            qB += __shfl_xor_sync(0xffffffffu, qB, 2);
            if ((lane & 3) == 0) {
                psum[lr0 * 8 + wn]       = sA;
                psq [lr0 * 8 + wn]       = qA;
                psum[(lr0 + 8) * 8 + wn] = sB;
                psq [(lr0 + 8) * 8 + wn] = qB;
            }
        }
        __syncthreads();
        #pragma unroll
        for (int mi = 0; mi < 4; mi++) {
            const int lr0 = wm * 64 + mi * 16 + qr;
            const int gr0 = bm + lr0;
            float s0 = 0.f, q0 = 0.f, s1 = 0.f, q1 = 0.f;
            #pragma unroll
            for (int w = 0; w < 8; w++) {
                s0 += psum[lr0 * 8 + w];
                q0 += psq [lr0 * 8 + w];
                s1 += psum[(lr0 + 8) * 8 + w];
                q1 += psq [(lr0 + 8) * 8 + w];
            }
            float m0 = s0 * (1.f / 256.f);
            float m1 = s1 * (1.f / 256.f);
            float r0v = rsqrtf(q0 * (1.f / 256.f) - m0 * m0 + EPS_);
            float r1v = rsqrtf(q1 * (1.f / 256.f) - m1 * m1 + EPS_);
            #pragma unroll
            for (int ni = 0; ni < 4; ni++) {
                const int cl = wn * 32 + ni * 8 + qc2;
                float g0 = __ldg(&gamma[cl]), g1 = __ldg(&gamma[cl + 1]);
                float e0 = __ldg(&beta[cl]),  e1 = __ldg(&beta[cl + 1]);
                float v00 = (acc[mi][ni][0] - m0) * r0v * g0 + e0;
                float v01 = (acc[mi][ni][1] - m0) * r0v * g1 + e1;
                float v10 = (acc[mi][ni][2] - m1) * r1v * g0 + e0;
                float v11 = (acc[mi][ni][3] - m1) * r1v * g1 + e1;
                *(float2*)&Cf[(size_t)gr0 * 256 + cl]       = make_float2(v00, v01);
                *(float2*)&Cf[(size_t)(gr0 + 8) * 256 + cl] = make_float2(v10, v11);
                uint32_t hi0 = packbf(v00, v01);
                uint32_t lo0 = packbf_lo(v00, v01, hi0);
                uint32_t hi1 = packbf(v10, v11);
                uint32_t lo1 = packbf_lo(v10, v11, hi1);
                *(uint32_t*)&U0[(size_t)gr0 * 256 + cl]       = hi0;
                *(uint32_t*)&U1[(size_t)gr0 * 256 + cl]       = lo0;
                *(uint32_t*)&U0[(size_t)(gr0 + 8) * 256 + cl] = hi1;
                *(uint32_t*)&U1[(size_t)(gr0 + 8) * 256 + cl] = lo1;
            }
        }
    }
}

// ---------------------------------------------------------------------------
// BatchNorm / misc helpers
// ---------------------------------------------------------------------------
__global__ void finalize_bn_kernel(const float* __restrict__ g,
                                   const float* __restrict__ b) {
    int c = threadIdx.x;
    float m  = g_sum[c]   * (1.f / (float)M_);
    float v  = g_sqsum[c] * (1.f / (float)M_) - m * m;
    float sc = g[c] * rsqrtf(v + EPS_);
    g_scale[c] = sc;
    g_shift[c] = b[c] - m * sc;
    g_sum[c] = 0.f; g_sqsum[c] = 0.f;
}

__global__ void deg_kernel(const int* __restrict__ adj) {
    int b = blockIdx.y;
    int n = blockIdx.x * 128 + threadIdx.x;
    const int* p = adj + (size_t)b * N_ * N_ + n;
    int s = 0;
    #pragma unroll 4
    for (int i = 0; i < N_; i++) s += (p[(size_t)i * N_] != 0);
    g_deg[b * N_ + n] = s;
}

__global__ void bn_deg_kernel(const float* __restrict__ A,
                              const float* __restrict__ deg_emb) {
    int idx = blockIdx.x * 256 + threadIdx.x;
    int row = idx >> 6;
    int c   = (idx & 63) << 2;
    float4 a = *(const float4*)&A[(size_t)row * D_ + c];
    const float* de = &deg_emb[(size_t)g_deg[row] * D_ + c];
    float y[4] = {a.x, a.y, a.z, a.w};
    float4 o; float* op = (float*)&o;
    #pragma unroll
    for (int k = 0; k < 4; k++) {
        float t = y[k] * g_scale[c + k] + g_shift[c + k];
        t = t >= 0.f ? t : 0.01f * t;
        op[k] = t + de[k];
    }
    size_t base = (size_t)row * D_ + c;
    *(float4*)&g_h[base] = o;
    #pragma unroll
    for (int k = 0; k < 4; k++) split_store(&g_h0[base + k], &g_h1[base + k], op[k]);
}

__global__ void bn_out_kernel(const float* __restrict__ A,
                              float* __restrict__ out) {
    int idx = blockIdx.x * 256 + threadIdx.x;
    int row = idx >> 6;
    int c   = (idx & 63) << 2;
    float4 a = *(const float4*)&A[(size_t)row * D_ + c];
    float y[4] = {a.x, a.y, a.z, a.w};
    float4 o; float* op = (float*)&o;
    #pragma unroll
    for (int k = 0; k < 4; k++) {
        float t = y[k] * g_scale[c + k] + g_shift[c + k];
        op[k] = t >= 0.f ? t : 0.01f * t;
    }
    *(float4*)&out[(size_t)row * D_ + c] = o;
}

// ---------------------------------------------------------------------------
// FlashAttention-style HMMA attention (unchanged)
// ---------------------------------------------------------------------------
#define APIT 40
#define VPIT 520
#define SM_Q0  0
#define SM_Q1  40960
#define SM_K0  81920
#define SM_K1  122880
#define SM_VT0 163840
#define SM_VT1 197120
#define SM_LUT 230400
#define ATTN_SMEM 230912

__global__ __launch_bounds__(256, 1) void attn_fa(
    const __nv_bfloat16* __restrict__ gS0, const __nv_bfloat16* __restrict__ gS1,
    const int* __restrict__ spd, const float* __restrict__ spd_emb,
    __nv_bfloat16* __restrict__ U0, __nv_bfloat16* __restrict__ U1)
{
    extern __shared__ char smem[];
    __nv_bfloat16* Q0s = (__nv_bfloat16*)(smem + SM_Q0);
    __nv_bfloat16* Q1s = (__nv_bfloat16*)(smem + SM_Q1);
    __nv_bfloat16* K0s = (__nv_bfloat16*)(smem + SM_K0);
    __nv_bfloat16* K1s = (__nv_bfloat16*)(smem + SM_K1);
    __nv_bfloat16* V0t = (__nv_bfloat16*)(smem + SM_VT0);
    __nv_bfloat16* V1t = (__nv_bfloat16*)(smem + SM_VT1);
    float*         SB2 = (float*)(smem + SM_LUT);

    const int bh = blockIdx.x;
    const int b  = bh >> 3;
    const int hh = bh & 7;
    const int b2 = bh & 31;
    const int ei = bh >> 5;
    const int tid  = threadIdx.x;
    const int wid  = tid >> 5;
    const int lane = tid & 31;

    const size_t rowbase = (size_t)b * 512 * 768;
    const int qcol = hh * 32;

    #pragma unroll
    for (int t = 0; t < 8; t++) {
        int id  = tid + t * 256;
        int row = id >> 2;
        int cb  = (id & 3) * 8;
        size_t g = rowbase + (size_t)row * 768;
        cp16(&Q0s[row * APIT + cb], &gS0[g + qcol + cb]);
        cp16(&Q1s[row * APIT + cb], &gS1[g + qcol + cb]);
        cp16(&K0s[row * APIT + cb], &gS0[g + 256 + qcol + cb]);
        cp16(&K1s[row * APIT + cb], &gS1[g + 256 + qcol + cb]);
    }
    CP_COMMIT();

    for (int idx = tid; idx < 2048; idx += 256) {
        int k  = idx >> 2;
        int dc = (idx & 3) * 8;
        size_t g = rowbase + (size_t)k * 768 + 512 + qcol + dc;
        uint4 v0 = *(const uint4*)&gS0[g];
        uint4 v1 = *(const uint4*)&gS1[g];
        const __nv_bfloat16* e0 = (const __nv_bfloat16*)&v0;
        const __nv_bfloat16* e1 = (const __nv_bfloat16*)&v1;
        #pragma unroll
        for (int e = 0; e < 8; e++) {
            V0t[(dc + e) * VPIT + k] = e0[e];
            V1t[(dc + e) * VPIT + k] = e1[e];
        }
    }
    if (tid < 100) SB2[tid + 1] = spd_emb[tid * H_ + ei];
    if (tid == 100) SB2[0] = -1.0f;
    CP_WAIT0();
    __syncthreads();

    const int R   = wid * 64;
    const int alr = lane & 15;
    const int alc = (lane >> 4) * 8;
    const int blr = lane & 7;
    const int blc = ((lane >> 3) & 1) * 8;
    const int qr  = lane >> 2;
    const int qc2 = (lane & 3) * 2;

    float o[4][4][4];
    float rsum[4][2];
    #pragma unroll
    for (int mi = 0; mi < 4; mi++) {
        rsum[mi][0] = 0.f; rsum[mi][1] = 0.f;
        #pragma unroll
        for (int ni = 0; ni < 4; ni++)
            #pragma unroll
            for (int k = 0; k < 4; k++) o[mi][ni][k] = 0.f;
    }

    for (int ch = 0; ch < 16; ch++) {
        const int KB = ch * 32;

        float sf[4][4][4];
        #pragma unroll
        for (int mi = 0; mi < 4; mi++)
            #pragma unroll
            for (int ni = 0; ni < 4; ni++)
                #pragma unroll
                for (int k = 0; k < 4; k++) sf[mi][ni][k] = 0.f;

        #pragma unroll
        for (int ks = 0; ks < 32; ks += 16) {
            uint32_t qa[4][4], kb0[4][2], kb1[4][2];
            #pragma unroll
            for (int mi = 0; mi < 4; mi++)
                ldmatrix_x4(qa[mi], &Q0s[(R + mi * 16 + alr) * APIT + ks + alc]);
            #pragma unroll
            for (int ni = 0; ni < 4; ni++)
                ldmatrix_x2(kb0[ni], &K0s[(KB + ni * 8 + blr) * APIT + ks + blc]);
            #pragma unroll
            for (int ni = 0; ni < 4; ni++)
                ldmatrix_x2(kb1[ni], &K1s[(KB + ni * 8 + blr) * APIT + ks + blc]);
            #pragma unroll
            for (int mi = 0; mi < 4; mi++)
                #pragma unroll
                for (int ni = 0; ni < 4; ni++) {
                    mma_bf16(sf[mi][ni], qa[mi], kb0[ni]);
                    mma_bf16(sf[mi][ni], qa[mi], kb1[ni]);
                }
            #pragma unroll
            for (int mi = 0; mi < 4; mi++)
                ldmatrix_x4(qa[mi], &Q1s[(R + mi * 16 + alr) * APIT + ks + alc]);
            #pragma unroll
            for (int mi = 0; mi < 4; mi++)
                #pragma unroll
                for (int ni = 0; ni < 4; ni++)
                    mma_bf16(sf[mi][ni], qa[mi], kb0[ni]);
        }

        #pragma unroll
        for (int mi = 0; mi < 4; mi++) {
            const int r0 = R + mi * 16 + qr;
            const int* sp0 = spd + ((size_t)b2 * 512 + r0) * 512;
            const int* sp1 = sp0 + 8 * 512;
            #pragma unroll
            for (int ni = 0; ni < 4; ni++) {
                const int kk = KB + ni * 8 + qc2;
                int2 sd0 = *(const int2*)&sp0[kk];
                int2 sd1 = *(const int2*)&sp1[kk];
                float p0 = __expf(sf[mi][ni][0] + SB2[sd0.x + 1]);
                float p1 = __expf(sf[mi][ni][1] + SB2[sd0.y + 1]);
                float p2 = __expf(sf[mi][ni][2] + SB2[sd1.x + 1]);
                float p3 = __expf(sf[mi][ni][3] + SB2[sd1.y + 1]);
                rsum[mi][0] += p0 + p1;
                rsum[mi][1] += p2 + p3;
                sf[mi][ni][0] = p0; sf[mi][ni][1] = p1;
                sf[mi][ni][2] = p2; sf[mi][ni][3] = p3;
            }
        }

        #pragma unroll
        for (int t = 0; t < 2; t++) {
            uint32_t pa0[4][4], pa1[4][4];
            #pragma unroll
            for (int mi = 0; mi < 4; mi++) {
                float* sA = sf[mi][2 * t];
                float* sB = sf[mi][2 * t + 1];
                pa0[mi][0] = packbf(sA[0], sA[1]);
                pa0[mi][1] = packbf(sA[2], sA[3]);
                pa0[mi][2] = packbf(sB[0], sB[1]);
                pa0[mi][3] = packbf(sB[2], sB[3]);
                pa1[mi][0] = packbf_lo(sA[0], sA[1], pa0[mi][0]);
                pa1[mi][1] = packbf_lo(sA[2], sA[3], pa0[mi][1]);
                pa1[mi][2] = packbf_lo(sB[0], sB[1], pa0[mi][2]);
                pa1[mi][3] = packbf_lo(sB[2], sB[3], pa0[mi][3]);
            }
            uint32_t vb0[4][2], vb1[4][2];
            #pragma unroll
            for (int ni = 0; ni < 4; ni++)
                ldmatrix_x2(vb0[ni], &V0t[(ni * 8 + blr) * VPIT + KB + t * 16 + blc]);
            #pragma unroll
            for (int ni = 0; ni < 4; ni++)
                ldmatrix_x2(vb1[ni], &V1t[(ni * 8 + blr) * VPIT + KB + t * 16 + blc]);
            #pragma unroll
            for (int mi = 0; mi < 4; mi++)
                #pragma unroll
                for (int ni = 0; ni < 4; ni++) {
                    mma_bf16(o[mi][ni], pa0[mi], vb0[ni]);
                    mma_bf16(o[mi][ni], pa1[mi], vb0[ni]);
                    mma_bf16(o[mi][ni], pa0[mi], vb1[ni]);
                }
        }
    }

    #pragma unroll
    for (int mi = 0; mi < 4; mi++) {
        float s0 = rsum[mi][0];
        s0 += __shfl_xor_sync(0xffffffffu, s0, 1);
        s0 += __shfl_xor_sync(0xffffffffu, s0, 2);
        float s1 = rsum[mi][1];
        s1 += __shfl_xor_sync(0xffffffffu, s1, 1);
        s1 += __shfl_xor_sync(0xffffffffu, s1, 2);
        float inv0 = 1.f / s0;
        float inv1 = 1.f / s1;
        const size_t gr0 = (size_t)b * 512 + R + mi * 16 + qr;
        #pragma unroll
        for (int ni = 0; ni < 4; ni++) {
            const int dh = qcol + ni * 8 + qc2;
            float v00 = o[mi][ni][0] * inv0;
            float v01 = o[mi][ni][1] * inv0;
            float v10 = o[mi][ni][2] * inv1;
            float v11 = o[mi][ni][3] * inv1;
            uint32_t hi0 = packbf(v00, v01);
            uint32_t lo0 = packbf_lo(v00, v01, hi0);
            uint32_t hi1 = packbf(v10, v11);
            uint32_t lo1 = packbf_lo(v10, v11, hi1);
            *(uint32_t*)&U0[gr0 * 256 + dh]       = hi0;
            *(uint32_t*)&U1[gr0 * 256 + dh]       = lo0;
            *(uint32_t*)&U0[(gr0 + 8) * 256 + dh] = hi1;
            *(uint32_t*)&U1[(gr0 + 8) * 256 + dh] = lo1;
        }
    }
}

// ---------------------------------------------------------------------------
// Launch. Slot 4 = first gemm_mma (ncu window).
// ---------------------------------------------------------------------------
extern "C" void kernel_launch(void* const* d_in, const int* in_sizes, int n_in,
                              void* d_out, int out_size) {
    const float* x       = (const float*)d_in[0];
    const int*   adj     = (const int*)  d_in[1];
    const int*   spd     = (const int*)  d_in[2];
    const float* W_first = (const float*)d_in[3];
    const float* b_first = (const float*)d_in[4];
    const float* bn1_g   = (const float*)d_in[5];
    const float* bn1_b   = (const float*)d_in[6];
    const float* deg_emb = (const float*)d_in[7];
    const float* spd_emb = (const float*)d_in[8];
    const float* Wqkv    = (const float*)d_in[9];
    const float* bqkv    = (const float*)d_in[10];
    const float* Wo      = (const float*)d_in[11];
    const float* bo      = (const float*)d_in[12];
    const float* ln1_g   = (const float*)d_in[13];
    const float* ln1_b   = (const float*)d_in[14];
    const float* W1      = (const float*)d_in[15];
    const float* b1      = (const float*)d_in[16];
    const float* W2      = (const float*)d_in[17];
    const float* b2      = (const float*)d_in[18];
    const float* ln2_g   = (const float*)d_in[19];
    const float* ln2_b   = (const float*)d_in[20];
    const float* W_in    = (const float*)d_in[21];
    const float* b_in    = (const float*)d_in[22];
    const float* bn2_g   = (const float*)d_in[23];
    const float* bn2_b   = (const float*)d_in[24];
    float* out = (float*)d_out;

    float *pH, *pT1;
    __nv_bfloat16 *pH0, *pH1, *pU0, *pU1, *pW0, *pW1, *pS0, *pS1;
    cudaGetSymbolAddress((void**)&pH,  g_h);
    cudaGetSymbolAddress((void**)&pT1, g_t1);
    cudaGetSymbolAddress((void**)&pH0, g_h0);
    cudaGetSymbolAddress((void**)&pH1, g_h1);
    cudaGetSymbolAddress((void**)&pU0, g_u0);
    cudaGetSymbolAddress((void**)&pU1, g_u1);
    cudaGetSymbolAddress((void**)&pW0, g_w0);
    cudaGetSymbolAddress((void**)&pW1, g_w1);
    cudaGetSymbolAddress((void**)&pS0, g_s0);
    cudaGetSymbolAddress((void**)&pS1, g_s1);

    cudaFuncSetAttribute(attn_fa,
                         cudaFuncAttributeMaxDynamicSharedMemorySize, ATTN_SMEM);
    cudaFuncSetAttribute(gemm_mma<0>,
                         cudaFuncAttributeMaxDynamicSharedMemorySize, GEMM_SMEM);
    cudaFuncSetAttribute(gemm_mma<1>,
                         cudaFuncAttributeMaxDynamicSharedMemorySize, GEMM_SMEM);
    cudaFuncSetAttribute(gemm_mma<2>,
                         cudaFuncAttributeMaxDynamicSharedMemorySize, GEMM_SMEM);
    cudaFuncSetAttribute(gemm_mma<3>,
                         cudaFuncAttributeMaxDynamicSharedMemorySize, GEMM_SMEM);

    const dim3 g1(128, 1), g3(128, 3);

    split_kernel<<<M_ * 64 / 256, 256>>>(x, pH0, pH1, M_ * 64);             // 1
    split5_kernel<<<512, 256>>>(W_first, Wo, W1, W2, W_in, pW0, pW1);       // 2
    deg_kernel<<<dim3(4, 32), 128>>>(adj);                                  // 3
    gemm_mma<0><<<g1, 512, GEMM_SMEM>>>(pH0, pH1, pW0 + OFF_FIRST,          // 4
                                        pW1 + OFF_FIRST, b_first, pT1,
                                        nullptr, nullptr, 256, nullptr, nullptr);
    split_kernel<<<384, 256>>>(Wqkv, pW0 + OFF_QKV, pW1 + OFF_QKV, 98304);  // 5
    finalize_bn_kernel<<<1, 256>>>(bn1_g, bn1_b);
    bn_deg_kernel<<<M_ * 64 / 256, 256>>>(pT1, deg_emb);

    for (int l = 0; l < L_; l++) {
        gemm_mma<2><<<g3, 512, GEMM_SMEM>>>(pH0, pH1,
            pW0 + OFF_QKV + (size_t)l * 196608, pW1 + OFF_QKV + (size_t)l * 196608,
            bqkv + l * 768, nullptr, pS0, pS1, 768, nullptr, nullptr);
        attn_fa<<<B_ * H_, 256, ATTN_SMEM>>>(pS0, pS1, spd, spd_emb, pU0, pU1);
        gemm_mma<3><<<g1, 512, GEMM_SMEM>>>(pU0, pU1,
            pW0 + OFF_WO + (size_t)l * 65536, pW1 + OFF_WO + (size_t)l * 65536,
            bo + l * 256, pH, pH0, pH1, 256, ln1_g + l * 256, ln1_b + l * 256);
        gemm_mma<1><<<g1, 512, GEMM_SMEM>>>(pH0, pH1,
            pW0 + OFF_W1 + (size_t)l * 65536, pW1 + OFF_W1 + (size_t)l * 65536,
            b1 + l * 256, nullptr, pU0, pU1, 256, nullptr, nullptr);
        gemm_mma<3><<<g1, 512, GEMM_SMEM>>>(pU0, pU1,
            pW0 + OFF_W2 + (size_t)l * 65536, pW1 + OFF_W2 + (size_t)l * 65536,
            b2 + l * 256, pH, pH0, pH1, 256, ln2_g + l * 256, ln2_b + l * 256);
    }

    gemm_mma<0><<<g1, 512, GEMM_SMEM>>>(pH0, pH1, pW0 + OFF_WIN, pW1 + OFF_WIN,
                                        b_in, pT1, nullptr, nullptr, 256,
                                        nullptr, nullptr);
    finalize_bn_kernel<<<1, 256>>>(bn2_g, bn2_b);
    bn_out_kernel<<<M_ * 64 / 256, 256>>>(pT1, out);
}

// round 14
// speedup vs baseline: 1.3470x; 1.3470x over previous
#include <cuda_runtime.h>
#include <cuda_bf16.h>
#include <math.h>
#include <stdint.h>

// ---------------------------------------------------------------------------
// Graphormer forward: B=32, N=512, D=256, H=8, DH=32, L=2
// GEMMs: mma.sync bf16 split-3-term, 128x256 CTA tile, 256 thr, warp 64x64,
//        3-stage cp.async, fused epilogues (colstats/relu/qkv/res+LN)
// Attention: FA-style register HMMA, 2 CTAs per (b,h) over query halves
// ---------------------------------------------------------------------------
#define B_   32
#define N_   512
#define D_   256
#define H_   8
#define DH_  32
#define L_   2
#define M_   (B_ * N_)
#define EPS_ 1e-5f

typedef unsigned long long u64;

// ---------------- scratch ----------------
__device__ float          g_h [M_ * D_];
__device__ float          g_t1[M_ * D_];
__device__ __nv_bfloat16  g_h0[M_ * D_];
__device__ __nv_bfloat16  g_h1[M_ * D_];
__device__ __nv_bfloat16  g_u0[M_ * D_];
__device__ __nv_bfloat16  g_u1[M_ * D_];
__device__ __nv_bfloat16  g_s0[M_ * 3 * D_];
__device__ __nv_bfloat16  g_s1[M_ * 3 * D_];
__device__ __nv_bfloat16  g_w0[917504];
__device__ __nv_bfloat16  g_w1[917504];
__device__ int            g_deg[M_];
__device__ float          g_sum[D_], g_sqsum[D_], g_scale[D_], g_shift[D_];

#define OFF_FIRST 0
#define OFF_QKV   65536
#define OFF_WO    458752
#define OFF_W1    589824
#define OFF_W2    720896
#define OFF_WIN   851968

// ---------------------------------------------------------------------------
// mma.sync / ldmatrix / cp.async helpers
// ---------------------------------------------------------------------------
__device__ __forceinline__ void mma_bf16(float* d, const uint32_t* a,
                                         const uint32_t* b) {
    asm volatile(
        "mma.sync.aligned.m16n8k16.row.col.f32.bf16.bf16.f32 "
        "{%0,%1,%2,%3}, {%4,%5,%6,%7}, {%8,%9}, {%0,%1,%2,%3};"
        : "+f"(d[0]), "+f"(d[1]), "+f"(d[2]), "+f"(d[3])
        : "r"(a[0]), "r"(a[1]), "r"(a[2]), "r"(a[3]), "r"(b[0]), "r"(b[1]));
}
__device__ __forceinline__ void ldmatrix_x4(uint32_t* r, const void* p) {
    uint32_t addr = (uint32_t)__cvta_generic_to_shared(p);
    asm volatile("ldmatrix.sync.aligned.m8n8.x4.shared.b16 {%0,%1,%2,%3}, [%4];"
                 : "=r"(r[0]), "=r"(r[1]), "=r"(r[2]), "=r"(r[3]) : "r"(addr));
}
__device__ __forceinline__ void ldmatrix_x2(uint32_t* r, const void* p) {
    uint32_t addr = (uint32_t)__cvta_generic_to_shared(p);
    asm volatile("ldmatrix.sync.aligned.m8n8.x2.shared.b16 {%0,%1}, [%2];"
                 : "=r"(r[0]), "=r"(r[1]) : "r"(addr));
}
__device__ __forceinline__ void cp16(void* smem, const void* gmem) {
    uint32_t s = (uint32_t)__cvta_generic_to_shared(smem);
    asm volatile("cp.async.cg.shared.global [%0], [%1], 16;"
                 :: "r"(s), "l"(gmem));
}
#define CP_COMMIT() asm volatile("cp.async.commit_group;" ::: "memory")
#define CP_WAIT2()  asm volatile("cp.async.wait_group 2;" ::: "memory")
#define CP_WAIT1()  asm volatile("cp.async.wait_group 1;" ::: "memory")
#define CP_WAIT0()  asm volatile("cp.async.wait_group 0;" ::: "memory")

__device__ __forceinline__ uint32_t packbf(float a, float b) {
    __nv_bfloat162 h;
    h.x = __float2bfloat16(a);
    h.y = __float2bfloat16(b);
    return *(uint32_t*)&h;
}
__device__ __forceinline__ uint32_t packbf_lo(float a, float b, uint32_t hi) {
    __nv_bfloat162 h = *(__nv_bfloat162*)&hi;
    return packbf(a - __bfloat162float(h.x), b - __bfloat162float(h.y));
}

// ---------------------------------------------------------------------------
// bf16 split helpers
// ---------------------------------------------------------------------------
__device__ __forceinline__ void split_store(__nv_bfloat16* p0, __nv_bfloat16* p1,
                                            float v) {
    __nv_bfloat16 b0 = __float2bfloat16(v);
    *p0 = b0;
    *p1 = __float2bfloat16(v - __bfloat162float(b0));
}

__device__ __forceinline__ void split4(const float* src,
                                       __nv_bfloat16* d0,
                                       __nv_bfloat16* d1, int i) {
    float4 v = ((const float4*)src)[i];
    __nv_bfloat162 h0a, h0b, h1a, h1b;
    h0a.x = __float2bfloat16(v.x);
    h0a.y = __float2bfloat16(v.y);
    h0b.x = __float2bfloat16(v.z);
    h0b.y = __float2bfloat16(v.w);
    h1a.x = __float2bfloat16(v.x - __bfloat162float(h0a.x));
    h1a.y = __float2bfloat16(v.y - __bfloat162float(h0a.y));
    h1b.x = __float2bfloat16(v.z - __bfloat162float(h0b.x));
    h1b.y = __float2bfloat16(v.w - __bfloat162float(h0b.y));
    ((__nv_bfloat162*)d0)[i * 2 + 0] = h0a;
    ((__nv_bfloat162*)d0)[i * 2 + 1] = h0b;
    ((__nv_bfloat162*)d1)[i * 2 + 0] = h1a;
    ((__nv_bfloat162*)d1)[i * 2 + 1] = h1b;
}

__global__ void split_kernel(const float* __restrict__ src,
                             __nv_bfloat16* __restrict__ d0,
                             __nv_bfloat16* __restrict__ d1, int n4) {
    int i = blockIdx.x * 256 + threadIdx.x;
    if (i >= n4) return;
    split4(src, d0, d1, i);
}

__global__ void split5_kernel(const float* __restrict__ Wf,
                              const float* __restrict__ Wo,
                              const float* __restrict__ W1f,
                              const float* __restrict__ W2f,
                              const float* __restrict__ Win,
                              __nv_bfloat16* __restrict__ w0,
                              __nv_bfloat16* __restrict__ w1) {
    int b = blockIdx.x;
    if (b == 0) {
        g_sum[threadIdx.x] = 0.f;
        g_sqsum[threadIdx.x] = 0.f;
    }
    const float* src; int base, rel;
    if (b < 64)       { src = Wf;  base = OFF_FIRST; rel = b; }
    else if (b < 192) { src = Wo;  base = OFF_WO;    rel = b - 64; }
    else if (b < 320) { src = W1f; base = OFF_W1;    rel = b - 192; }
    else if (b < 448) { src = W2f; base = OFF_W2;    rel = b - 320; }
    else              { src = Win; base = OFF_WIN;   rel = b - 448; }
    int i = rel * 256 + threadIdx.x;
    split4(src, w0 + base, w1 + base, i);
}

// ---------------------------------------------------------------------------
// GEMM: 128x256 CTA tile, 256 threads (8 warps 2x4), warp tile 64x64,
// BK=32, K=256, 3-stage cp.async. Epilogues as in R11.
// ---------------------------------------------------------------------------
#define PADK     40
#define A_TILE_B (128 * PADK * 2)
#define W_TILE_B (256 * PADK * 2)
#define STAGE_B  (2 * A_TILE_B + 2 * W_TILE_B)   // 61440
#define HDR_B    5120
#define GEMM_SMEM (HDR_B + 3 * STAGE_B)          // 189440

__device__ __forceinline__ void load_stage(
    char* buf, const __nv_bfloat16* A0, const __nv_bfloat16* A1,
    const __nv_bfloat16* W0, const __nv_bfloat16* W1,
    int bm, int bn, int k0, int tid)
{
    #pragma unroll
    for (int i = 0; i < 4; i++) {
        int id  = tid + i * 256;
        int s   = id >> 9;
        int row = (id >> 2) & 127;
        int cb  = id & 3;
        const __nv_bfloat16* src = s ? A1 : A0;
        cp16(buf + s * A_TILE_B + row * 80 + cb * 16,
             &src[(size_t)(bm + row) * 256 + k0 + cb * 8]);
    }
    char* wb = buf + 2 * A_TILE_B;
    #pragma unroll
    for (int i = 0; i < 8; i++) {
        int id  = tid + i * 256;
        int s   = id >> 10;
        int row = (id >> 2) & 255;
        int cb  = id & 3;
        const __nv_bfloat16* src = s ? W1 : W0;
        cp16(wb + s * W_TILE_B + row * 80 + cb * 16,
             &src[(size_t)(bn + row) * 256 + k0 + cb * 8]);
    }
}

template <int EPI>
__global__ __launch_bounds__(256) void gemm_mma(
    const __nv_bfloat16* __restrict__ A0, const __nv_bfloat16* __restrict__ A1,
    const __nv_bfloat16* __restrict__ W0, const __nv_bfloat16* __restrict__ W1,
    const float* __restrict__ bias, float* __restrict__ Cf,
    __nv_bfloat16* __restrict__ U0, __nv_bfloat16* __restrict__ U1, int Nc,
    const float* __restrict__ gamma, const float* __restrict__ beta)
{
    extern __shared__ char smem[];
    float* bsm  = (float*)smem;                 // [256]
    float* psum = (float*)(smem + 1024);        // [128][4]
    float* psq  = (float*)(smem + 3072);        // [128][4]

    const int tid  = threadIdx.x;
    const int wid  = tid >> 5;
    const int lane = tid & 31;
    const int bm   = blockIdx.x * 128;
    const int bn   = blockIdx.y * 256;
    const int wm   = wid >> 2;
    const int wn   = wid & 3;

    bsm[tid] = bias[bn + tid];

    float acc[4][8][4];
    #pragma unroll
    for (int mi = 0; mi < 4; mi++)
        #pragma unroll
        for (int ni = 0; ni < 8; ni++)
            #pragma unroll
            for (int k = 0; k < 4; k++) acc[mi][ni][k] = 0.f;

    const int alr = lane & 15;
    const int alc = (lane >> 4) * 8;
    const int blr = lane & 7;
    const int blc = ((lane >> 3) & 1) * 8;

    load_stage(smem + HDR_B + 0 * STAGE_B, A0, A1, W0, W1, bm, bn, 0,  tid);
    CP_COMMIT();
    load_stage(smem + HDR_B + 1 * STAGE_B, A0, A1, W0, W1, bm, bn, 32, tid);
    CP_COMMIT();

    #pragma unroll
    for (int c = 0; c < 8; c++) {
        if (c + 2 < 8) {
            load_stage(smem + HDR_B + ((c + 2) % 3) * STAGE_B,
                       A0, A1, W0, W1, bm, bn, (c + 2) * 32, tid);
            CP_COMMIT();
            CP_WAIT2();
        } else if (c + 1 < 8) {
            CP_WAIT1();
        } else {
            CP_WAIT0();
        }
        __syncthreads();

        char* buf = smem + HDR_B + (c % 3) * STAGE_B;
        __nv_bfloat16* A0s = (__nv_bfloat16*)(buf);
        __nv_bfloat16* A1s = (__nv_bfloat16*)(buf + A_TILE_B);
        __nv_bfloat16* W0s = (__nv_bfloat16*)(buf + 2 * A_TILE_B);
        __nv_bfloat16* W1s = (__nv_bfloat16*)(buf + 2 * A_TILE_B + W_TILE_B);

        #pragma unroll
        for (int ks = 0; ks < 32; ks += 16) {
            uint32_t af[4][4], w0f[8][2], w1f[8][2];
            #pragma unroll
            for (int mi = 0; mi < 4; mi++)
                ldmatrix_x4(af[mi],
                    &A0s[(wm * 64 + mi * 16 + alr) * PADK + ks + alc]);
            #pragma unroll
            for (int ni = 0; ni < 8; ni++)
                ldmatrix_x2(w0f[ni],
                    &W0s[(wn * 64 + ni * 8 + blr) * PADK + ks + blc]);
            #pragma unroll
            for (int ni = 0; ni < 8; ni++)
                ldmatrix_x2(w1f[ni],
                    &W1s[(wn * 64 + ni * 8 + blr) * PADK + ks + blc]);

            #pragma unroll
            for (int mi = 0; mi < 4; mi++)
                #pragma unroll
                for (int ni = 0; ni < 8; ni++) {
                    mma_bf16(acc[mi][ni], af[mi], w0f[ni]);
                    mma_bf16(acc[mi][ni], af[mi], w1f[ni]);
                }
            #pragma unroll
            for (int mi = 0; mi < 4; mi++)
                ldmatrix_x4(af[mi],
                    &A1s[(wm * 64 + mi * 16 + alr) * PADK + ks + alc]);
            #pragma unroll
            for (int mi = 0; mi < 4; mi++)
                #pragma unroll
                for (int ni = 0; ni < 8; ni++)
                    mma_bf16(acc[mi][ni], af[mi], w0f[ni]);
        }
        __syncthreads();
    }

    const int qr  = lane >> 2;
    const int qc2 = (lane & 3) * 2;

    if (EPI == 0) {
        #pragma unroll
        for (int ni = 0; ni < 8; ni++) {
            const int cl = wn * 64 + ni * 8 + qc2;
            const int gc = bn + cl;
            float cs0 = 0.f, cs1 = 0.f, cq0 = 0.f, cq1 = 0.f;
            #pragma unroll
            for (int mi = 0; mi < 4; mi++) {
                const int r0 = bm + wm * 64 + mi * 16 + qr;
                float v00 = acc[mi][ni][0] + bsm[cl];
                float v01 = acc[mi][ni][1] + bsm[cl + 1];
                float v10 = acc[mi][ni][2] + bsm[cl];
                float v11 = acc[mi][ni][3] + bsm[cl + 1];
                *(float2*)&Cf[(size_t)r0 * Nc + gc]       = make_float2(v00, v01);
                *(float2*)&Cf[(size_t)(r0 + 8) * Nc + gc] = make_float2(v10, v11);
                cs0 += v00 + v10; cs1 += v01 + v11;
                cq0 += v00 * v00 + v10 * v10;
                cq1 += v01 * v01 + v11 * v11;
            }
            #pragma unroll
            for (int off = 4; off <= 16; off <<= 1) {
                cs0 += __shfl_xor_sync(0xffffffffu, cs0, off);
                cs1 += __shfl_xor_sync(0xffffffffu, cs1, off);
                cq0 += __shfl_xor_sync(0xffffffffu, cq0, off);
                cq1 += __shfl_xor_sync(0xffffffffu, cq1, off);
            }
            if (qr == 0) {
                atomicAdd(&g_sum[gc],       cs0);
                atomicAdd(&g_sum[gc + 1],   cs1);
                atomicAdd(&g_sqsum[gc],     cq0);
                atomicAdd(&g_sqsum[gc + 1], cq1);
            }
        }
    } else if (EPI == 1 || EPI == 2) {
        const float esc = (EPI == 2 && blockIdx.y == 0) ? 0.17677669529663687f
                                                        : 1.0f;
        #pragma unroll
        for (int mi = 0; mi < 4; mi++) {
            #pragma unroll
            for (int ni = 0; ni < 8; ni++) {
                const int cl = wn * 64 + ni * 8 + qc2;
                const int gc = bn + cl;
                const int r0 = bm + wm * 64 + mi * 16 + qr;
                float v00 = acc[mi][ni][0] + bsm[cl];
                float v01 = acc[mi][ni][1] + bsm[cl + 1];
                float v10 = acc[mi][ni][2] + bsm[cl];
                float v11 = acc[mi][ni][3] + bsm[cl + 1];
                if (EPI == 1) {
                    v00 = fmaxf(v00, 0.f); v01 = fmaxf(v01, 0.f);
                    v10 = fmaxf(v10, 0.f); v11 = fmaxf(v11, 0.f);
                } else {
                    v00 *= esc; v01 *= esc; v10 *= esc; v11 *= esc;
                }
                uint32_t hi0 = packbf(v00, v01);
                uint32_t lo0 = packbf_lo(v00, v01, hi0);
                uint32_t hi1 = packbf(v10, v11);
                uint32_t lo1 = packbf_lo(v10, v11, hi1);
                *(uint32_t*)&U0[(size_t)r0 * Nc + gc]       = hi0;
                *(uint32_t*)&U1[(size_t)r0 * Nc + gc]       = lo0;
                *(uint32_t*)&U0[(size_t)(r0 + 8) * Nc + gc] = hi1;
                *(uint32_t*)&U1[(size_t)(r0 + 8) * Nc + gc] = lo1;
            }
        }
    } else {
        #pragma unroll
        for (int mi = 0; mi < 4; mi++) {
            const int lr0 = wm * 64 + mi * 16 + qr;
            const int gr0 = bm + lr0;
            float sA = 0.f, qA = 0.f, sB = 0.f, qB = 0.f;
            #pragma unroll
            for (int ni = 0; ni < 8; ni++) {
                const int cl = wn * 64 + ni * 8 + qc2;
                float2 h0v = *(float2*)&Cf[(size_t)gr0 * 256 + cl];
                float2 h1v = *(float2*)&Cf[(size_t)(gr0 + 8) * 256 + cl];
                float v00 = acc[mi][ni][0] + bsm[cl]     + h0v.x;
                float v01 = acc[mi][ni][1] + bsm[cl + 1] + h0v.y;
                float v10 = acc[mi][ni][2] + bsm[cl]     + h1v.x;
                float v11 = acc[mi][ni][3] + bsm[cl + 1] + h1v.y;
                acc[mi][ni][0] = v00; acc[mi][ni][1] = v01;
                acc[mi][ni][2] = v10; acc[mi][ni][3] = v11;
                sA += v00 + v01; qA += v00 * v00 + v01 * v01;
                sB += v10 + v11; qB += v10 * v10 + v11 * v11;
            }
            sA += __shfl_xor_sync(0xffffffffu, sA, 1);
            sA += __shfl_xor_sync(0xffffffffu, sA, 2);
            qA += __shfl_xor_sync(0xffffffffu, qA, 1);
            qA += __shfl_xor_sync(0xffffffffu, qA, 2);
            sB += __shfl_xor_sync(0xffffffffu, sB, 1);
            sB += __shfl_xor_sync(0xffffffffu, sB, 2);
            qB += __shfl_xor_sync(0xffffffffu, qB, 1);
            qB += __shfl_xor_sync(0xffffffffu, qB, 2);
            if ((lane & 3) == 0) {
                psum[lr0 * 4 + wn]       = sA;
                psq [lr0 * 4 + wn]       = qA;
                psum[(lr0 + 8) * 4 + wn] = sB;
                psq [(lr0 + 8) * 4 + wn] = qB;
            }
        }
        __syncthreads();
        #pragma unroll
        for (int mi = 0; mi < 4; mi++) {
            const int lr0 = wm * 64 + mi * 16 + qr;
            const int gr0 = bm + lr0;
            float s0 = psum[lr0 * 4] + psum[lr0 * 4 + 1]
                     + psum[lr0 * 4 + 2] + psum[lr0 * 4 + 3];
            float q0 = psq[lr0 * 4] + psq[lr0 * 4 + 1]
                     + psq[lr0 * 4 + 2] + psq[lr0 * 4 + 3];
            float s1 = psum[(lr0 + 8) * 4] + psum[(lr0 + 8) * 4 + 1]
                     + psum[(lr0 + 8) * 4 + 2] + psum[(lr0 + 8) * 4 + 3];
            float q1 = psq[(lr0 + 8) * 4] + psq[(lr0 + 8) * 4 + 1]
                     + psq[(lr0 + 8) * 4 + 2] + psq[(lr0 + 8) * 4 + 3];
            float m0 = s0 * (1.f / 256.f);
            float m1 = s1 * (1.f / 256.f);
            float r0v = rsqrtf(q0 * (1.f / 256.f) - m0 * m0 + EPS_);
            float r1v = rsqrtf(q1 * (1.f / 256.f) - m1 * m1 + EPS_);
            #pragma unroll
            for (int ni = 0; ni < 8; ni++) {
                const int cl = wn * 64 + ni * 8 + qc2;
                float g0 = __ldg(&gamma[cl]), g1 = __ldg(&gamma[cl + 1]);
                float e0 = __ldg(&beta[cl]),  e1 = __ldg(&beta[cl + 1]);
                float v00 = (acc[mi][ni][0] - m0) * r0v * g0 + e0;
                float v01 = (acc[mi][ni][1] - m0) * r0v * g1 + e1;
                float v10 = (acc[mi][ni][2] - m1) * r1v * g0 + e0;
                float v11 = (acc[mi][ni][3] - m1) * r1v * g1 + e1;
                *(float2*)&Cf[(size_t)gr0 * 256 + cl]       = make_float2(v00, v01);
                *(float2*)&Cf[(size_t)(gr0 + 8) * 256 + cl] = make_float2(v10, v11);
                uint32_t hi0 = packbf(v00, v01);
                uint32_t lo0 = packbf_lo(v00, v01, hi0);
                uint32_t hi1 = packbf(v10, v11);
                uint32_t lo1 = packbf_lo(v10, v11, hi1);
                *(uint32_t*)&U0[(size_t)gr0 * 256 + cl]       = hi0;
                *(uint32_t*)&U1[(size_t)gr0 * 256 + cl]       = lo0;
                *(uint32_t*)&U0[(size_t)(gr0 + 8) * 256 + cl] = hi1;
                *(uint32_t*)&U1[(size_t)(gr0 + 8) * 256 + cl] = lo1;
            }
        }
    }
}

// ---------------------------------------------------------------------------
// BatchNorm / misc helpers
// ---------------------------------------------------------------------------
__global__ void finalize_bn_kernel(const float* __restrict__ g,
                                   const float* __restrict__ b) {
    int c = threadIdx.x;
    float m  = g_sum[c]   * (1.f / (float)M_);
    float v  = g_sqsum[c] * (1.f / (float)M_) - m * m;
    float sc = g[c] * rsqrtf(v + EPS_);
    g_scale[c] = sc;
    g_shift[c] = b[c] - m * sc;
    g_sum[c] = 0.f; g_sqsum[c] = 0.f;
}

__global__ void deg_kernel(const int* __restrict__ adj) {
    int b = blockIdx.y;
    int n = blockIdx.x * 128 + threadIdx.x;
    const int* p = adj + (size_t)b * N_ * N_ + n;
    int s = 0;
    #pragma unroll 4
    for (int i = 0; i < N_; i++) s += (p[(size_t)i * N_] != 0);
    g_deg[b * N_ + n] = s;
}

__global__ void bn_deg_kernel(const float* __restrict__ A,
                              const float* __restrict__ deg_emb) {
    int idx = blockIdx.x * 256 + threadIdx.x;
    int row = idx >> 6;
    int c   = (idx & 63) << 2;
    float4 a = *(const float4*)&A[(size_t)row * D_ + c];
    const float* de = &deg_emb[(size_t)g_deg[row] * D_ + c];
    float y[4] = {a.x, a.y, a.z, a.w};
    float4 o; float* op = (float*)&o;
    #pragma unroll
    for (int k = 0; k < 4; k++) {
        float t = y[k] * g_scale[c + k] + g_shift[c + k];
        t = t >= 0.f ? t : 0.01f * t;
        op[k] = t + de[k];
    }
    size_t base = (size_t)row * D_ + c;
    *(float4*)&g_h[base] = o;
    #pragma unroll
    for (int k = 0; k < 4; k++) split_store(&g_h0[base + k], &g_h1[base + k], op[k]);
}

__global__ void bn_out_kernel(const float* __restrict__ A,
                              float* __restrict__ out) {
    int idx = blockIdx.x * 256 + threadIdx.x;
    int row = idx >> 6;
    int c   = (idx & 63) << 2;
    float4 a = *(const float4*)&A[(size_t)row * D_ + c];
    float y[4] = {a.x, a.y, a.z, a.w};
    float4 o; float* op = (float*)&o;
    #pragma unroll
    for (int k = 0; k < 4; k++) {
        float t = y[k] * g_scale[c + k] + g_shift[c + k];
        op[k] = t >= 0.f ? t : 0.01f * t;
    }
    *(float4*)&out[(size_t)row * D_ + c] = o;
}

// ---------------------------------------------------------------------------
// FA-style HMMA attention, 2 CTAs per (b,h): blockIdx.x = bh*2 + half.
// Each CTA: 256 query rows (8 warps x 32 rows), full K + V^T in smem.
// ---------------------------------------------------------------------------
#define APIT 40
#define VPIT 520
#define SM_Q0  0                       // 256 rows * 40 * 2 = 20480
#define SM_Q1  20480
#define SM_K0  40960                   // 512 rows * 40 * 2 = 40960
#define SM_K1  81920
#define SM_VT0 122880                  // 32 * 520 * 2 = 33280
#define SM_VT1 156160
#define SM_LUT 189440
#define ATTN_SMEM 189952

__global__ __launch_bounds__(256, 1) void attn_fa(
    const __nv_bfloat16* __restrict__ gS0, const __nv_bfloat16* __restrict__ gS1,
    const int* __restrict__ spd, const float* __restrict__ spd_emb,
    __nv_bfloat16* __restrict__ U0, __nv_bfloat16* __restrict__ U1)
{
    extern __shared__ char smem[];
    __nv_bfloat16* Q0s = (__nv_bfloat16*)(smem + SM_Q0);
    __nv_bfloat16* Q1s = (__nv_bfloat16*)(smem + SM_Q1);
    __nv_bfloat16* K0s = (__nv_bfloat16*)(smem + SM_K0);
    __nv_bfloat16* K1s = (__nv_bfloat16*)(smem + SM_K1);
    __nv_bfloat16* V0t = (__nv_bfloat16*)(smem + SM_VT0);
    __nv_bfloat16* V1t = (__nv_bfloat16*)(smem + SM_VT1);
    float*         SB2 = (float*)(smem + SM_LUT);

    const int bh   = blockIdx.x >> 1;
    const int half = blockIdx.x & 1;
    const int b  = bh >> 3;
    const int hh = bh & 7;
    const int b2 = bh & 31;
    const int ei = bh >> 5;
    const int tid  = threadIdx.x;
    const int wid  = tid >> 5;
    const int lane = tid & 31;

    const size_t rowbase = (size_t)b * 512 * 768;
    const int qcol  = hh * 32;
    const int qbase = half * 256;          // global query-row offset

    // Q half: 256 rows x 4 chunks, both splits per id
    #pragma unroll
    for (int t = 0; t < 4; t++) {
        int id  = tid + t * 256;           // 0..1023
        int row = id >> 2;
        int cb  = (id & 3) * 8;
        size_t g = rowbase + (size_t)(qbase + row) * 768 + qcol + cb;
        cp16(&Q0s[row * APIT + cb], &gS0[g]);
        cp16(&Q1s[row * APIT + cb], &gS1[g]);
    }
    // K full: 512 rows x 4 chunks, both splits per id
    #pragma unroll
    for (int t = 0; t < 8; t++) {
        int id  = tid + t * 256;           // 0..2047
        int row = id >> 2;
        int cb  = (id & 3) * 8;
        size_t g = rowbase + (size_t)row * 768 + 256 + qcol + cb;
        cp16(&K0s[row * APIT + cb], &gS0[g]);
        cp16(&K1s[row * APIT + cb], &gS1[g]);
    }
    CP_COMMIT();

    for (int idx = tid; idx < 2048; idx += 256) {
        int k  = idx >> 2;
        int dc = (idx & 3) * 8;
        size_t g = rowbase + (size_t)k * 768 + 512 + qcol + dc;
        uint4 v0 = *(const uint4*)&gS0[g];
        uint4 v1 = *(const uint4*)&gS1[g];
        const __nv_bfloat16* e0 = (const __nv_bfloat16*)&v0;
        const __nv_bfloat16* e1 = (const __nv_bfloat16*)&v1;
        #pragma unroll
        for (int e = 0; e < 8; e++) {
            V0t[(dc + e) * VPIT + k] = e0[e];
            V1t[(dc + e) * VPIT + k] = e1[e];
        }
    }
    if (tid < 100) SB2[tid + 1] = spd_emb[tid * H_ + ei];
    if (tid == 100) SB2[0] = -1.0f;
    CP_WAIT0();
    __syncthreads();

    const int R   = wid * 32;              // local query base (8 warps x 32)
    const int alr = lane & 15;
    const int alc = (lane >> 4) * 8;
    const int blr = lane & 7;
    const int blc = ((lane >> 3) & 1) * 8;
    const int qr  = lane >> 2;
    const int qc2 = (lane & 3) * 2;

    float o[2][4][4];
    float rsum[2][2];
    #pragma unroll
    for (int mi = 0; mi < 2; mi++) {
        rsum[mi][0] = 0.f; rsum[mi][1] = 0.f;
        #pragma unroll
        for (int ni = 0; ni < 4; ni++)
            #pragma unroll
            for (int k = 0; k < 4; k++) o[mi][ni][k] = 0.f;
    }

    for (int ch = 0; ch < 16; ch++) {
        const int KB = ch * 32;

        float sf[2][4][4];
        #pragma unroll
        for (int mi = 0; mi < 2; mi++)
            #pragma unroll
            for (int ni = 0; ni < 4; ni++)
                #pragma unroll
                for (int k = 0; k < 4; k++) sf[mi][ni][k] = 0.f;

        #pragma unroll
        for (int ks = 0; ks < 32; ks += 16) {
            uint32_t qa[2][4], kb0[4][2], kb1[4][2];
            #pragma unroll
            for (int mi = 0; mi < 2; mi++)
                ldmatrix_x4(qa[mi], &Q0s[(R + mi * 16 + alr) * APIT + ks + alc]);
            #pragma unroll
            for (int ni = 0; ni < 4; ni++)
                ldmatrix_x2(kb0[ni], &K0s[(KB + ni * 8 + blr) * APIT + ks + blc]);
            #pragma unroll
            for (int ni = 0; ni < 4; ni++)
                ldmatrix_x2(kb1[ni], &K1s[(KB + ni * 8 + blr) * APIT + ks + blc]);
            #pragma unroll
            for (int mi = 0; mi < 2; mi++)
                #pragma unroll
                for (int ni = 0; ni < 4; ni++) {
                    mma_bf16(sf[mi][ni], qa[mi], kb0[ni]);
                    mma_bf16(sf[mi][ni], qa[mi], kb1[ni]);
                }
            #pragma unroll
            for (int mi = 0; mi < 2; mi++)
                ldmatrix_x4(qa[mi], &Q1s[(R + mi * 16 + alr) * APIT + ks + alc]);
            #pragma unroll
            for (int mi = 0; mi < 2; mi++)
                #pragma unroll
                for (int ni = 0; ni < 4; ni++)
                    mma_bf16(sf[mi][ni], qa[mi], kb0[ni]);
        }

        #pragma unroll
        for (int mi = 0; mi < 2; mi++) {
            const int r0 = qbase + R + mi * 16 + qr;
            const int* sp0 = spd + ((size_t)b2 * 512 + r0) * 512;
            const int* sp1 = sp0 + 8 * 512;
            #pragma unroll
            for (int ni = 0; ni < 4; ni++) {
                const int kk = KB + ni * 8 + qc2;
                int2 sd0 = *(const int2*)&sp0[kk];
                int2 sd1 = *(const int2*)&sp1[kk];
                float p0 = __expf(sf[mi][ni][0] + SB2[sd0.x + 1]);
                float p1 = __expf(sf[mi][ni][1] + SB2[sd0.y + 1]);
                float p2 = __expf(sf[mi][ni][2] + SB2[sd1.x + 1]);
                float p3 = __expf(sf[mi][ni][3] + SB2[sd1.y + 1]);
                rsum[mi][0] += p0 + p1;
                rsum[mi][1] += p2 + p3;
                sf[mi][ni][0] = p0; sf[mi][ni][1] = p1;
                sf[mi][ni][2] = p2; sf[mi][ni][3] = p3;
            }
        }

        #pragma unroll
        for (int t = 0; t < 2; t++) {
            uint32_t pa0[2][4], pa1[2][4];
            #pragma unroll
            for (int mi = 0; mi < 2; mi++) {
                float* sA = sf[mi][2 * t];
                float* sB = sf[mi][2 * t + 1];
                pa0[mi][0] = packbf(sA[0], sA[1]);
                pa0[mi][1] = packbf(sA[2], sA[3]);
                pa0[mi][2] = packbf(sB[0], sB[1]);
                pa0[mi][3] = packbf(sB[2], sB[3]);
                pa1[mi][0] = packbf_lo(sA[0], sA[1], pa0[mi][0]);
                pa1[mi][1] = packbf_lo(sA[2], sA[3], pa0[mi][1]);
                pa1[mi][2] = packbf_lo(sB[0], sB[1], pa0[mi][2]);
                pa1[mi][3] = packbf_lo(sB[2], sB[3], pa0[mi][3]);
            }
            uint32_t vb0[4][2], vb1[4][2];
            #pragma unroll
            for (int ni = 0; ni < 4; ni++)
                ldmatrix_x2(vb0[ni], &V0t[(ni * 8 + blr) * VPIT + KB + t * 16 + blc]);
            #pragma unroll
            for (int ni = 0; ni < 4; ni++)
                ldmatrix_x2(vb1[ni], &V1t[(ni * 8 + blr) * VPIT + KB + t * 16 + blc]);
            #pragma unroll
            for (int mi = 0; mi < 2; mi++)
                #pragma unroll
                for (int ni = 0; ni < 4; ni++) {
                    mma_bf16(o[mi][ni], pa0[mi], vb0[ni]);
                    mma_bf16(o[mi][ni], pa1[mi], vb0[ni]);
                    mma_bf16(o[mi][ni], pa0[mi], vb1[ni]);
                }
        }
    }

    #pragma unroll
    for (int mi = 0; mi < 2; mi++) {
        float s0 = rsum[mi][0];
        s0 += __shfl_xor_sync(0xffffffffu, s0, 1);
        s0 += __shfl_xor_sync(0xffffffffu, s0, 2);
        float s1 = rsum[mi][1];
        s1 += __shfl_xor_sync(0xffffffffu, s1, 1);
        s1 += __shfl_xor_sync(0xffffffffu, s1, 2);
        float inv0 = 1.f / s0;
        float inv1 = 1.f / s1;
        const size_t gr0 = (size_t)b * 512 + qbase + R + mi * 16 + qr;
        #pragma unroll
        for (int ni = 0; ni < 4; ni++) {
            const int dh = qcol + ni * 8 + qc2;
            float v00 = o[mi][ni][0] * inv0;
            float v01 = o[mi][ni][1] * inv0;
            float v10 = o[mi][ni][2] * inv1;
            float v11 = o[mi][ni][3] * inv1;
            uint32_t hi0 = packbf(v00, v01);
            uint32_t lo0 = packbf_lo(v00, v01, hi0);
            uint32_t hi1 = packbf(v10, v11);
            uint32_t lo1 = packbf_lo(v10, v11, hi1);
            *(uint32_t*)&U0[gr0 * 256 + dh]       = hi0;
            *(uint32_t*)&U1[gr0 * 256 + dh]       = lo0;
            *(uint32_t*)&U0[(gr0 + 8) * 256 + dh] = hi1;
            *(uint32_t*)&U1[(gr0 + 8) * 256 + dh] = lo1;
        }
    }
}

// ---------------------------------------------------------------------------
// Launch. Slot 4 = first gemm_mma (ncu window).
// ---------------------------------------------------------------------------
extern "C" void kernel_launch(void* const* d_in, const int* in_sizes, int n_in,
                              void* d_out, int out_size) {
    const float* x       = (const float*)d_in[0];
    const int*   adj     = (const int*)  d_in[1];
    const int*   spd     = (const int*)  d_in[2];
    const float* W_first = (const float*)d_in[3];
    const float* b_first = (const float*)d_in[4];
    const float* bn1_g   = (const float*)d_in[5];
    const float* bn1_b   = (const float*)d_in[6];
    const float* deg_emb = (const float*)d_in[7];
    const float* spd_emb = (const float*)d_in[8];
    const float* Wqkv    = (const float*)d_in[9];
    const float* bqkv    = (const float*)d_in[10];
    const float* Wo      = (const float*)d_in[11];
    const float* bo      = (const float*)d_in[12];
    const float* ln1_g   = (const float*)d_in[13];
    const float* ln1_b   = (const float*)d_in[14];
    const float* W1      = (const float*)d_in[15];
    const float* b1      = (const float*)d_in[16];
    const float* W2      = (const float*)d_in[17];
    const float* b2      = (const float*)d_in[18];
    const float* ln2_g   = (const float*)d_in[19];
    const float* ln2_b   = (const float*)d_in[20];
    const float* W_in    = (const float*)d_in[21];
    const float* b_in    = (const float*)d_in[22];
    const float* bn2_g   = (const float*)d_in[23];
    const float* bn2_b   = (const float*)d_in[24];
    float* out = (float*)d_out;

    float *pH, *pT1;
    __nv_bfloat16 *pH0, *pH1, *pU0, *pU1, *pW0, *pW1, *pS0, *pS1;
    cudaGetSymbolAddress((void**)&pH,  g_h);
    cudaGetSymbolAddress((void**)&pT1, g_t1);
    cudaGetSymbolAddress((void**)&pH0, g_h0);
    cudaGetSymbolAddress((void**)&pH1, g_h1);
    cudaGetSymbolAddress((void**)&pU0, g_u0);
    cudaGetSymbolAddress((void**)&pU1, g_u1);
    cudaGetSymbolAddress((void**)&pW0, g_w0);
    cudaGetSymbolAddress((void**)&pW1, g_w1);
    cudaGetSymbolAddress((void**)&pS0, g_s0);
    cudaGetSymbolAddress((void**)&pS1, g_s1);

    cudaFuncSetAttribute(attn_fa,
                         cudaFuncAttributeMaxDynamicSharedMemorySize, ATTN_SMEM);
    cudaFuncSetAttribute(gemm_mma<0>,
                         cudaFuncAttributeMaxDynamicSharedMemorySize, GEMM_SMEM);
    cudaFuncSetAttribute(gemm_mma<1>,
                         cudaFuncAttributeMaxDynamicSharedMemorySize, GEMM_SMEM);
    cudaFuncSetAttribute(gemm_mma<2>,
                         cudaFuncAttributeMaxDynamicSharedMemorySize, GEMM_SMEM);
    cudaFuncSetAttribute(gemm_mma<3>,
                         cudaFuncAttributeMaxDynamicSharedMemorySize, GEMM_SMEM);

    const dim3 g1(128, 1), g3(128, 3);

    split_kernel<<<M_ * 64 / 256, 256>>>(x, pH0, pH1, M_ * 64);             // 1
    split5_kernel<<<512, 256>>>(W_first, Wo, W1, W2, W_in, pW0, pW1);       // 2
    deg_kernel<<<dim3(4, 32), 128>>>(adj);                                  // 3
    gemm_mma<0><<<g1, 256, GEMM_SMEM>>>(pH0, pH1, pW0 + OFF_FIRST,          // 4
                                        pW1 + OFF_FIRST, b_first, pT1,
                                        nullptr, nullptr, 256, nullptr, nullptr);
    split_kernel<<<384, 256>>>(Wqkv, pW0 + OFF_QKV, pW1 + OFF_QKV, 98304);  // 5
    finalize_bn_kernel<<<1, 256>>>(bn1_g, bn1_b);
    bn_deg_kernel<<<M_ * 64 / 256, 256>>>(pT1, deg_emb);

    for (int l = 0; l < L_; l++) {
        gemm_mma<2><<<g3, 256, GEMM_SMEM>>>(pH0, pH1,
            pW0 + OFF_QKV + (size_t)l * 196608, pW1 + OFF_QKV + (size_t)l * 196608,
            bqkv + l * 768, nullptr, pS0, pS1, 768, nullptr, nullptr);
        attn_fa<<<B_ * H_ * 2, 256, ATTN_SMEM>>>(pS0, pS1, spd, spd_emb, pU0, pU1);
        gemm_mma<3><<<g1, 256, GEMM_SMEM>>>(pU0, pU1,
            pW0 + OFF_WO + (size_t)l * 65536, pW1 + OFF_WO + (size_t)l * 65536,
            bo + l * 256, pH, pH0, pH1, 256, ln1_g + l * 256, ln1_b + l * 256);
        gemm_mma<1><<<g1, 256, GEMM_SMEM>>>(pH0, pH1,
            pW0 + OFF_W1 + (size_t)l * 65536, pW1 + OFF_W1 + (size_t)l * 65536,
            b1 + l * 256, nullptr, pU0, pU1, 256, nullptr, nullptr);
        gemm_mma<3><<<g1, 256, GEMM_SMEM>>>(pU0, pU1,
            pW0 + OFF_W2 + (size_t)l * 65536, pW1 + OFF_W2 + (size_t)l * 65536,
            b2 + l * 256, pH, pH0, pH1, 256, ln2_g + l * 256, ln2_b + l * 256);
    }

    gemm_mma<0><<<g1, 256, GEMM_SMEM>>>(pH0, pH1, pW0 + OFF_WIN, pW1 + OFF_WIN,
                                        b_in, pT1, nullptr, nullptr, 256,
                                        nullptr, nullptr);
    finalize_bn_kernel<<<1, 256>>>(bn2_g, bn2_b);
    bn_out_kernel<<<M_ * 64 / 256, 256>>>(pT1, out);
}

// round 15
// speedup vs baseline: 1.4644x; 1.0871x over previous
#include <cuda_runtime.h>
#include <cuda_bf16.h>
#include <math.h>
#include <stdint.h>

// ---------------------------------------------------------------------------
// Graphormer forward: B=32, N=512, D=256, H=8, DH=32, L=2
// GEMMs: mma.sync bf16 split-3-term, 128x256 CTA tile, 256 thr, warp 64x64,
//        2-stage cp.async (R11 config), fused epilogues
// Attention: FA-style register HMMA, one (b,h) per CTA, 512 threads
// ---------------------------------------------------------------------------
#define B_   32
#define N_   512
#define D_   256
#define H_   8
#define DH_  32
#define L_   2
#define M_   (B_ * N_)
#define EPS_ 1e-5f

typedef unsigned long long u64;

// ---------------- scratch ----------------
__device__ float          g_h [M_ * D_];
__device__ float          g_t1[M_ * D_];
__device__ __nv_bfloat16  g_h0[M_ * D_];
__device__ __nv_bfloat16  g_h1[M_ * D_];
__device__ __nv_bfloat16  g_u0[M_ * D_];
__device__ __nv_bfloat16  g_u1[M_ * D_];
__device__ __nv_bfloat16  g_s0[M_ * 3 * D_];
__device__ __nv_bfloat16  g_s1[M_ * 3 * D_];
__device__ __nv_bfloat16  g_w0[917504];
__device__ __nv_bfloat16  g_w1[917504];
__device__ int            g_deg[M_];
__device__ float          g_sum[D_], g_sqsum[D_], g_scale[D_], g_shift[D_];

#define OFF_FIRST 0
#define OFF_QKV   65536
#define OFF_WO    458752
#define OFF_W1    589824
#define OFF_W2    720896
#define OFF_WIN   851968

// ---------------------------------------------------------------------------
// mma.sync / ldmatrix / cp.async helpers
// ---------------------------------------------------------------------------
__device__ __forceinline__ void mma_bf16(float* d, const uint32_t* a,
                                         const uint32_t* b) {
    asm volatile(
        "mma.sync.aligned.m16n8k16.row.col.f32.bf16.bf16.f32 "
        "{%0,%1,%2,%3}, {%4,%5,%6,%7}, {%8,%9}, {%0,%1,%2,%3};"
        : "+f"(d[0]), "+f"(d[1]), "+f"(d[2]), "+f"(d[3])
        : "r"(a[0]), "r"(a[1]), "r"(a[2]), "r"(a[3]), "r"(b[0]), "r"(b[1]));
}
__device__ __forceinline__ void ldmatrix_x4(uint32_t* r, const void* p) {
    uint32_t addr = (uint32_t)__cvta_generic_to_shared(p);
    asm volatile("ldmatrix.sync.aligned.m8n8.x4.shared.b16 {%0,%1,%2,%3}, [%4];"
                 : "=r"(r[0]), "=r"(r[1]), "=r"(r[2]), "=r"(r[3]) : "r"(addr));
}
__device__ __forceinline__ void ldmatrix_x2(uint32_t* r, const void* p) {
    uint32_t addr = (uint32_t)__cvta_generic_to_shared(p);
    asm volatile("ldmatrix.sync.aligned.m8n8.x2.shared.b16 {%0,%1}, [%2];"
                 : "=r"(r[0]), "=r"(r[1]) : "r"(addr));
}
__device__ __forceinline__ void cp16(void* smem, const void* gmem) {
    uint32_t s = (uint32_t)__cvta_generic_to_shared(smem);
    asm volatile("cp.async.cg.shared.global [%0], [%1], 16;"
                 :: "r"(s), "l"(gmem));
}
#define CP_COMMIT() asm volatile("cp.async.commit_group;" ::: "memory")
#define CP_WAIT1()  asm volatile("cp.async.wait_group 1;" ::: "memory")
#define CP_WAIT0()  asm volatile("cp.async.wait_group 0;" ::: "memory")

__device__ __forceinline__ uint32_t packbf(float a, float b) {
    __nv_bfloat162 h;
    h.x = __float2bfloat16(a);
    h.y = __float2bfloat16(b);
    return *(uint32_t*)&h;
}
__device__ __forceinline__ uint32_t packbf_lo(float a, float b, uint32_t hi) {
    __nv_bfloat162 h = *(__nv_bfloat162*)&hi;
    return packbf(a - __bfloat162float(h.x), b - __bfloat162float(h.y));
}

// ---------------------------------------------------------------------------
// bf16 split helpers
// ---------------------------------------------------------------------------
__device__ __forceinline__ void split_store(__nv_bfloat16* p0, __nv_bfloat16* p1,
                                            float v) {
    __nv_bfloat16 b0 = __float2bfloat16(v);
    *p0 = b0;
    *p1 = __float2bfloat16(v - __bfloat162float(b0));
}

__device__ __forceinline__ void split4(const float* src,
                                       __nv_bfloat16* d0,
                                       __nv_bfloat16* d1, int i) {
    float4 v = ((const float4*)src)[i];
    __nv_bfloat162 h0a, h0b, h1a, h1b;
    h0a.x = __float2bfloat16(v.x);
    h0a.y = __float2bfloat16(v.y);
    h0b.x = __float2bfloat16(v.z);
    h0b.y = __float2bfloat16(v.w);
    h1a.x = __float2bfloat16(v.x - __bfloat162float(h0a.x));
    h1a.y = __float2bfloat16(v.y - __bfloat162float(h0a.y));
    h1b.x = __float2bfloat16(v.z - __bfloat162float(h0b.x));
    h1b.y = __float2bfloat16(v.w - __bfloat162float(h0b.y));
    ((__nv_bfloat162*)d0)[i * 2 + 0] = h0a;
    ((__nv_bfloat162*)d0)[i * 2 + 1] = h0b;
    ((__nv_bfloat162*)d1)[i * 2 + 0] = h1a;
    ((__nv_bfloat162*)d1)[i * 2 + 1] = h1b;
}

__global__ void split_kernel(const float* __restrict__ src,
                             __nv_bfloat16* __restrict__ d0,
                             __nv_bfloat16* __restrict__ d1, int n4) {
    int i = blockIdx.x * 256 + threadIdx.x;
    if (i >= n4) return;
    split4(src, d0, d1, i);
}

__global__ void split5_kernel(const float* __restrict__ Wf,
                              const float* __restrict__ Wo,
                              const float* __restrict__ W1f,
                              const float* __restrict__ W2f,
                              const float* __restrict__ Win,
                              __nv_bfloat16* __restrict__ w0,
                              __nv_bfloat16* __restrict__ w1) {
    int b = blockIdx.x;
    if (b == 0) {
        g_sum[threadIdx.x] = 0.f;
        g_sqsum[threadIdx.x] = 0.f;
    }
    const float* src; int base, rel;
    if (b < 64)       { src = Wf;  base = OFF_FIRST; rel = b; }
    else if (b < 192) { src = Wo;  base = OFF_WO;    rel = b - 64; }
    else if (b < 320) { src = W1f; base = OFF_W1;    rel = b - 192; }
    else if (b < 448) { src = W2f; base = OFF_W2;    rel = b - 320; }
    else              { src = Win; base = OFF_WIN;   rel = b - 448; }
    int i = rel * 256 + threadIdx.x;
    split4(src, w0 + base, w1 + base, i);
}

// ---------------------------------------------------------------------------
// GEMM: 128x256 CTA tile, 256 threads (8 warps 2x4), warp tile 64x64,
// BK=32, K=256, 2-stage cp.async (R11 config). Epilogues:
//   EPI 0: fp32 + colstats. EPI 1: relu+splits. EPI 2: qkv splits (Q scaled).
//   EPI 3: residual + LayerNorm + fp32 & splits.
// ---------------------------------------------------------------------------
#define PADK     40
#define A_TILE_B (128 * PADK * 2)
#define W_TILE_B (256 * PADK * 2)
#define STAGE_B  (2 * A_TILE_B + 2 * W_TILE_B)   // 61440
#define HDR_B    5120
#define GEMM_SMEM (HDR_B + 2 * STAGE_B)          // 128000

__device__ __forceinline__ void load_stage(
    char* buf, const __nv_bfloat16* A0, const __nv_bfloat16* A1,
    const __nv_bfloat16* W0, const __nv_bfloat16* W1,
    int bm, int bn, int k0, int tid)
{
    #pragma unroll
    for (int i = 0; i < 4; i++) {
        int id  = tid + i * 256;
        int s   = id >> 9;
        int row = (id >> 2) & 127;
        int cb  = id & 3;
        const __nv_bfloat16* src = s ? A1 : A0;
        cp16(buf + s * A_TILE_B + row * 80 + cb * 16,
             &src[(size_t)(bm + row) * 256 + k0 + cb * 8]);
    }
    char* wb = buf + 2 * A_TILE_B;
    #pragma unroll
    for (int i = 0; i < 8; i++) {
        int id  = tid + i * 256;
        int s   = id >> 10;
        int row = (id >> 2) & 255;
        int cb  = id & 3;
        const __nv_bfloat16* src = s ? W1 : W0;
        cp16(wb + s * W_TILE_B + row * 80 + cb * 16,
             &src[(size_t)(bn + row) * 256 + k0 + cb * 8]);
    }
}

template <int EPI>
__global__ __launch_bounds__(256) void gemm_mma(
    const __nv_bfloat16* __restrict__ A0, const __nv_bfloat16* __restrict__ A1,
    const __nv_bfloat16* __restrict__ W0, const __nv_bfloat16* __restrict__ W1,
    const float* __restrict__ bias, float* __restrict__ Cf,
    __nv_bfloat16* __restrict__ U0, __nv_bfloat16* __restrict__ U1, int Nc,
    const float* __restrict__ gamma, const float* __restrict__ beta)
{
    extern __shared__ char smem[];
    float* bsm  = (float*)smem;                 // [256]
    float* psum = (float*)(smem + 1024);        // [128][4]
    float* psq  = (float*)(smem + 3072);        // [128][4]

    const int tid  = threadIdx.x;
    const int wid  = tid >> 5;
    const int lane = tid & 31;
    const int bm   = blockIdx.x * 128;
    const int bn   = blockIdx.y * 256;
    const int wm   = wid >> 2;
    const int wn   = wid & 3;

    bsm[tid] = bias[bn + tid];

    float acc[4][8][4];
    #pragma unroll
    for (int mi = 0; mi < 4; mi++)
        #pragma unroll
        for (int ni = 0; ni < 8; ni++)
            #pragma unroll
            for (int k = 0; k < 4; k++) acc[mi][ni][k] = 0.f;

    const int alr = lane & 15;
    const int alc = (lane >> 4) * 8;
    const int blr = lane & 7;
    const int blc = ((lane >> 3) & 1) * 8;

    load_stage(smem + HDR_B, A0, A1, W0, W1, bm, bn, 0, tid);
    CP_COMMIT();

    #pragma unroll
    for (int c = 0; c < 8; c++) {
        if (c < 7) {
            load_stage(smem + HDR_B + ((c + 1) & 1) * STAGE_B,
                       A0, A1, W0, W1, bm, bn, (c + 1) * 32, tid);
            CP_COMMIT();
            CP_WAIT1();
        } else {
            CP_WAIT0();
        }
        __syncthreads();

        char* buf = smem + HDR_B + (c & 1) * STAGE_B;
        __nv_bfloat16* A0s = (__nv_bfloat16*)(buf);
        __nv_bfloat16* A1s = (__nv_bfloat16*)(buf + A_TILE_B);
        __nv_bfloat16* W0s = (__nv_bfloat16*)(buf + 2 * A_TILE_B);
        __nv_bfloat16* W1s = (__nv_bfloat16*)(buf + 2 * A_TILE_B + W_TILE_B);

        #pragma unroll
        for (int ks = 0; ks < 32; ks += 16) {
            uint32_t af[4][4], w0f[8][2], w1f[8][2];
            #pragma unroll
            for (int mi = 0; mi < 4; mi++)
                ldmatrix_x4(af[mi],
                    &A0s[(wm * 64 + mi * 16 + alr) * PADK + ks + alc]);
            #pragma unroll
            for (int ni = 0; ni < 8; ni++)
                ldmatrix_x2(w0f[ni],
                    &W0s[(wn * 64 + ni * 8 + blr) * PADK + ks + blc]);
            #pragma unroll
            for (int ni = 0; ni < 8; ni++)
                ldmatrix_x2(w1f[ni],
                    &W1s[(wn * 64 + ni * 8 + blr) * PADK + ks + blc]);

            #pragma unroll
            for (int mi = 0; mi < 4; mi++)
                #pragma unroll
                for (int ni = 0; ni < 8; ni++) {
                    mma_bf16(acc[mi][ni], af[mi], w0f[ni]);
                    mma_bf16(acc[mi][ni], af[mi], w1f[ni]);
                }
            #pragma unroll
            for (int mi = 0; mi < 4; mi++)
                ldmatrix_x4(af[mi],
                    &A1s[(wm * 64 + mi * 16 + alr) * PADK + ks + alc]);
            #pragma unroll
            for (int mi = 0; mi < 4; mi++)
                #pragma unroll
                for (int ni = 0; ni < 8; ni++)
                    mma_bf16(acc[mi][ni], af[mi], w0f[ni]);
        }
        __syncthreads();
    }

    const int qr  = lane >> 2;
    const int qc2 = (lane & 3) * 2;

    if (EPI == 0) {
        #pragma unroll
        for (int ni = 0; ni < 8; ni++) {
            const int cl = wn * 64 + ni * 8 + qc2;
            const int gc = bn + cl;
            float cs0 = 0.f, cs1 = 0.f, cq0 = 0.f, cq1 = 0.f;
            #pragma unroll
            for (int mi = 0; mi < 4; mi++) {
                const int r0 = bm + wm * 64 + mi * 16 + qr;
                float v00 = acc[mi][ni][0] + bsm[cl];
                float v01 = acc[mi][ni][1] + bsm[cl + 1];
                float v10 = acc[mi][ni][2] + bsm[cl];
                float v11 = acc[mi][ni][3] + bsm[cl + 1];
                *(float2*)&Cf[(size_t)r0 * Nc + gc]       = make_float2(v00, v01);
                *(float2*)&Cf[(size_t)(r0 + 8) * Nc + gc] = make_float2(v10, v11);
                cs0 += v00 + v10; cs1 += v01 + v11;
                cq0 += v00 * v00 + v10 * v10;
                cq1 += v01 * v01 + v11 * v11;
            }
            #pragma unroll
            for (int off = 4; off <= 16; off <<= 1) {
                cs0 += __shfl_xor_sync(0xffffffffu, cs0, off);
                cs1 += __shfl_xor_sync(0xffffffffu, cs1, off);
                cq0 += __shfl_xor_sync(0xffffffffu, cq0, off);
                cq1 += __shfl_xor_sync(0xffffffffu, cq1, off);
            }
            if (qr == 0) {
                atomicAdd(&g_sum[gc],       cs0);
                atomicAdd(&g_sum[gc + 1],   cs1);
                atomicAdd(&g_sqsum[gc],     cq0);
                atomicAdd(&g_sqsum[gc + 1], cq1);
            }
        }
    } else if (EPI == 1 || EPI == 2) {
        const float esc = (EPI == 2 && blockIdx.y == 0) ? 0.17677669529663687f
                                                        : 1.0f;
        #pragma unroll
        for (int mi = 0; mi < 4; mi++) {
            #pragma unroll
            for (int ni = 0; ni < 8; ni++) {
                const int cl = wn * 64 + ni * 8 + qc2;
                const int gc = bn + cl;
                const int r0 = bm + wm * 64 + mi * 16 + qr;
                float v00 = acc[mi][ni][0] + bsm[cl];
                float v01 = acc[mi][ni][1] + bsm[cl + 1];
                float v10 = acc[mi][ni][2] + bsm[cl];
                float v11 = acc[mi][ni][3] + bsm[cl + 1];
                if (EPI == 1) {
                    v00 = fmaxf(v00, 0.f); v01 = fmaxf(v01, 0.f);
                    v10 = fmaxf(v10, 0.f); v11 = fmaxf(v11, 0.f);
                } else {
                    v00 *= esc; v01 *= esc; v10 *= esc; v11 *= esc;
                }
                uint32_t hi0 = packbf(v00, v01);
                uint32_t lo0 = packbf_lo(v00, v01, hi0);
                uint32_t hi1 = packbf(v10, v11);
                uint32_t lo1 = packbf_lo(v10, v11, hi1);
                *(uint32_t*)&U0[(size_t)r0 * Nc + gc]       = hi0;
                *(uint32_t*)&U1[(size_t)r0 * Nc + gc]       = lo0;
                *(uint32_t*)&U0[(size_t)(r0 + 8) * Nc + gc] = hi1;
                *(uint32_t*)&U1[(size_t)(r0 + 8) * Nc + gc] = lo1;
            }
        }
    } else {
        #pragma unroll
        for (int mi = 0; mi < 4; mi++) {
            const int lr0 = wm * 64 + mi * 16 + qr;
            const int gr0 = bm + lr0;
            float sA = 0.f, qA = 0.f, sB = 0.f, qB = 0.f;
            #pragma unroll
            for (int ni = 0; ni < 8; ni++) {
                const int cl = wn * 64 + ni * 8 + qc2;
                float2 h0v = *(float2*)&Cf[(size_t)gr0 * 256 + cl];
                float2 h1v = *(float2*)&Cf[(size_t)(gr0 + 8) * 256 + cl];
                float v00 = acc[mi][ni][0] + bsm[cl]     + h0v.x;
                float v01 = acc[mi][ni][1] + bsm[cl + 1] + h0v.y;
                float v10 = acc[mi][ni][2] + bsm[cl]     + h1v.x;
                float v11 = acc[mi][ni][3] + bsm[cl + 1] + h1v.y;
                acc[mi][ni][0] = v00; acc[mi][ni][1] = v01;
                acc[mi][ni][2] = v10; acc[mi][ni][3] = v11;
                sA += v00 + v01; qA += v00 * v00 + v01 * v01;
                sB += v10 + v11; qB += v10 * v10 + v11 * v11;
            }
            sA += __shfl_xor_sync(0xffffffffu, sA, 1);
            sA += __shfl_xor_sync(0xffffffffu, sA, 2);
            qA += __shfl_xor_sync(0xffffffffu, qA, 1);
            qA += __shfl_xor_sync(0xffffffffu, qA, 2);
            sB += __shfl_xor_sync(0xffffffffu, sB, 1);
            sB += __shfl_xor_sync(0xffffffffu, sB, 2);
            qB += __shfl_xor_sync(0xffffffffu, qB, 1);
            qB += __shfl_xor_sync(0xffffffffu, qB, 2);
            if ((lane & 3) == 0) {
                psum[lr0 * 4 + wn]       = sA;
                psq [lr0 * 4 + wn]       = qA;
                psum[(lr0 + 8) * 4 + wn] = sB;
                psq [(lr0 + 8) * 4 + wn] = qB;
            }
        }
        __syncthreads();
        #pragma unroll
        for (int mi = 0; mi < 4; mi++) {
            const int lr0 = wm * 64 + mi * 16 + qr;
            const int gr0 = bm + lr0;
            float s0 = psum[lr0 * 4] + psum[lr0 * 4 + 1]
                     + psum[lr0 * 4 + 2] + psum[lr0 * 4 + 3];
            float q0 = psq[lr0 * 4] + psq[lr0 * 4 + 1]
                     + psq[lr0 * 4 + 2] + psq[lr0 * 4 + 3];
            float s1 = psum[(lr0 + 8) * 4] + psum[(lr0 + 8) * 4 + 1]
                     + psum[(lr0 + 8) * 4 + 2] + psum[(lr0 + 8) * 4 + 3];
            float q1 = psq[(lr0 + 8) * 4] + psq[(lr0 + 8) * 4 + 1]
                     + psq[(lr0 + 8) * 4 + 2] + psq[(lr0 + 8) * 4 + 3];
            float m0 = s0 * (1.f / 256.f);
            float m1 = s1 * (1.f / 256.f);
            float r0v = rsqrtf(q0 * (1.f / 256.f) - m0 * m0 + EPS_);
            float r1v = rsqrtf(q1 * (1.f / 256.f) - m1 * m1 + EPS_);
            #pragma unroll
            for (int ni = 0; ni < 8; ni++) {
                const int cl = wn * 64 + ni * 8 + qc2;
                float g0 = __ldg(&gamma[cl]), g1 = __ldg(&gamma[cl + 1]);
                float e0 = __ldg(&beta[cl]),  e1 = __ldg(&beta[cl + 1]);
                float v00 = (acc[mi][ni][0] - m0) * r0v * g0 + e0;
                float v01 = (acc[mi][ni][1] - m0) * r0v * g1 + e1;
                float v10 = (acc[mi][ni][2] - m1) * r1v * g0 + e0;
                float v11 = (acc[mi][ni][3] - m1) * r1v * g1 + e1;
                *(float2*)&Cf[(size_t)gr0 * 256 + cl]       = make_float2(v00, v01);
                *(float2*)&Cf[(size_t)(gr0 + 8) * 256 + cl] = make_float2(v10, v11);
                uint32_t hi0 = packbf(v00, v01);
                uint32_t lo0 = packbf_lo(v00, v01, hi0);
                uint32_t hi1 = packbf(v10, v11);
                uint32_t lo1 = packbf_lo(v10, v11, hi1);
                *(uint32_t*)&U0[(size_t)gr0 * 256 + cl]       = hi0;
                *(uint32_t*)&U1[(size_t)gr0 * 256 + cl]       = lo0;
                *(uint32_t*)&U0[(size_t)(gr0 + 8) * 256 + cl] = hi1;
                *(uint32_t*)&U1[(size_t)(gr0 + 8) * 256 + cl] = lo1;
            }
        }
    }
}

// ---------------------------------------------------------------------------
// BatchNorm / misc helpers
// ---------------------------------------------------------------------------
__global__ void finalize_bn_kernel(const float* __restrict__ g,
                                   const float* __restrict__ b) {
    int c = threadIdx.x;
    float m  = g_sum[c]   * (1.f / (float)M_);
    float v  = g_sqsum[c] * (1.f / (float)M_) - m * m;
    float sc = g[c] * rsqrtf(v + EPS_);
    g_scale[c] = sc;
    g_shift[c] = b[c] - m * sc;
    g_sum[c] = 0.f; g_sqsum[c] = 0.f;
}

__global__ void deg_kernel(const int* __restrict__ adj) {
    int b = blockIdx.y;
    int n = blockIdx.x * 128 + threadIdx.x;
    const int* p = adj + (size_t)b * N_ * N_ + n;
    int s = 0;
    #pragma unroll 4
    for (int i = 0; i < N_; i++) s += (p[(size_t)i * N_] != 0);
    g_deg[b * N_ + n] = s;
}

__global__ void bn_deg_kernel(const float* __restrict__ A,
                              const float* __restrict__ deg_emb) {
    int idx = blockIdx.x * 256 + threadIdx.x;
    int row = idx >> 6;
    int c   = (idx & 63) << 2;
    float4 a = *(const float4*)&A[(size_t)row * D_ + c];
    const float* de = &deg_emb[(size_t)g_deg[row] * D_ + c];
    float y[4] = {a.x, a.y, a.z, a.w};
    float4 o; float* op = (float*)&o;
    #pragma unroll
    for (int k = 0; k < 4; k++) {
        float t = y[k] * g_scale[c + k] + g_shift[c + k];
        t = t >= 0.f ? t : 0.01f * t;
        op[k] = t + de[k];
    }
    size_t base = (size_t)row * D_ + c;
    *(float4*)&g_h[base] = o;
    #pragma unroll
    for (int k = 0; k < 4; k++) split_store(&g_h0[base + k], &g_h1[base + k], op[k]);
}

__global__ void bn_out_kernel(const float* __restrict__ A,
                              float* __restrict__ out) {
    int idx = blockIdx.x * 256 + threadIdx.x;
    int row = idx >> 6;
    int c   = (idx & 63) << 2;
    float4 a = *(const float4*)&A[(size_t)row * D_ + c];
    float y[4] = {a.x, a.y, a.z, a.w};
    float4 o; float* op = (float*)&o;
    #pragma unroll
    for (int k = 0; k < 4; k++) {
        float t = y[k] * g_scale[c + k] + g_shift[c + k];
        op[k] = t >= 0.f ? t : 0.01f * t;
    }
    *(float4*)&out[(size_t)row * D_ + c] = o;
}

// ---------------------------------------------------------------------------
// FA-style HMMA attention: one (b,h) per CTA, 512 threads (16 warps,
// 32 query rows each). Single prologue per CTA (Q/K cp.async, V transpose).
// ---------------------------------------------------------------------------
#define APIT 40
#define VPIT 520
#define SM_Q0  0
#define SM_Q1  40960
#define SM_K0  81920
#define SM_K1  122880
#define SM_VT0 163840
#define SM_VT1 197120
#define SM_LUT 230400
#define ATTN_SMEM 230912

__global__ __launch_bounds__(512, 1) void attn_fa(
    const __nv_bfloat16* __restrict__ gS0, const __nv_bfloat16* __restrict__ gS1,
    const int* __restrict__ spd, const float* __restrict__ spd_emb,
    __nv_bfloat16* __restrict__ U0, __nv_bfloat16* __restrict__ U1)
{
    extern __shared__ char smem[];
    __nv_bfloat16* Q0s = (__nv_bfloat16*)(smem + SM_Q0);
    __nv_bfloat16* Q1s = (__nv_bfloat16*)(smem + SM_Q1);
    __nv_bfloat16* K0s = (__nv_bfloat16*)(smem + SM_K0);
    __nv_bfloat16* K1s = (__nv_bfloat16*)(smem + SM_K1);
    __nv_bfloat16* V0t = (__nv_bfloat16*)(smem + SM_VT0);
    __nv_bfloat16* V1t = (__nv_bfloat16*)(smem + SM_VT1);
    float*         SB2 = (float*)(smem + SM_LUT);

    const int bh = blockIdx.x;
    const int b  = bh >> 3;
    const int hh = bh & 7;
    const int b2 = bh & 31;
    const int ei = bh >> 5;
    const int tid  = threadIdx.x;
    const int wid  = tid >> 5;
    const int lane = tid & 31;

    const size_t rowbase = (size_t)b * 512 * 768;
    const int qcol = hh * 32;

    // prologue: Q/K (512 rows x 4 chunks each, both splits per id)
    #pragma unroll
    for (int t = 0; t < 4; t++) {
        int id  = tid + t * 512;           // 0..2047
        int row = id >> 2;
        int cb  = (id & 3) * 8;
        size_t g = rowbase + (size_t)row * 768;
        cp16(&Q0s[row * APIT + cb], &gS0[g + qcol + cb]);
        cp16(&Q1s[row * APIT + cb], &gS1[g + qcol + cb]);
        cp16(&K0s[row * APIT + cb], &gS0[g + 256 + qcol + cb]);
        cp16(&K1s[row * APIT + cb], &gS1[g + 256 + qcol + cb]);
    }
    CP_COMMIT();

    // V transpose: [key][dh] -> V^T [dh][key]
    for (int idx = tid; idx < 2048; idx += 512) {
        int k  = idx >> 2;
        int dc = (idx & 3) * 8;
        size_t g = rowbase + (size_t)k * 768 + 512 + qcol + dc;
        uint4 v0 = *(const uint4*)&gS0[g];
        uint4 v1 = *(const uint4*)&gS1[g];
        const __nv_bfloat16* e0 = (const __nv_bfloat16*)&v0;
        const __nv_bfloat16* e1 = (const __nv_bfloat16*)&v1;
        #pragma unroll
        for (int e = 0; e < 8; e++) {
            V0t[(dc + e) * VPIT + k] = e0[e];
            V1t[(dc + e) * VPIT + k] = e1[e];
        }
    }
    if (tid < 100) SB2[tid + 1] = spd_emb[tid * H_ + ei];
    if (tid == 100) SB2[0] = -1.0f;
    CP_WAIT0();
    __syncthreads();

    const int R   = wid * 32;              // 16 warps x 32 rows
    const int alr = lane & 15;
    const int alc = (lane >> 4) * 8;
    const int blr = lane & 7;
    const int blc = ((lane >> 3) & 1) * 8;
    const int qr  = lane >> 2;
    const int qc2 = (lane & 3) * 2;

    float o[2][4][4];
    float rsum[2][2];
    #pragma unroll
    for (int mi = 0; mi < 2; mi++) {
        rsum[mi][0] = 0.f; rsum[mi][1] = 0.f;
        #pragma unroll
        for (int ni = 0; ni < 4; ni++)
            #pragma unroll
            for (int k = 0; k < 4; k++) o[mi][ni][k] = 0.f;
    }

    for (int ch = 0; ch < 16; ch++) {
        const int KB = ch * 32;

        float sf[2][4][4];
        #pragma unroll
        for (int mi = 0; mi < 2; mi++)
            #pragma unroll
            for (int ni = 0; ni < 4; ni++)
                #pragma unroll
                for (int k = 0; k < 4; k++) sf[mi][ni][k] = 0.f;

        #pragma unroll
        for (int ks = 0; ks < 32; ks += 16) {
            uint32_t qa[2][4], kb0[4][2], kb1[4][2];
            #pragma unroll
            for (int mi = 0; mi < 2; mi++)
                ldmatrix_x4(qa[mi], &Q0s[(R + mi * 16 + alr) * APIT + ks + alc]);
            #pragma unroll
            for (int ni = 0; ni < 4; ni++)
                ldmatrix_x2(kb0[ni], &K0s[(KB + ni * 8 + blr) * APIT + ks + blc]);
            #pragma unroll
            for (int ni = 0; ni < 4; ni++)
                ldmatrix_x2(kb1[ni], &K1s[(KB + ni * 8 + blr) * APIT + ks + blc]);
            #pragma unroll
            for (int mi = 0; mi < 2; mi++)
                #pragma unroll
                for (int ni = 0; ni < 4; ni++) {
                    mma_bf16(sf[mi][ni], qa[mi], kb0[ni]);
                    mma_bf16(sf[mi][ni], qa[mi], kb1[ni]);
                }
            #pragma unroll
            for (int mi = 0; mi < 2; mi++)
                ldmatrix_x4(qa[mi], &Q1s[(R + mi * 16 + alr) * APIT + ks + alc]);
            #pragma unroll
            for (int mi = 0; mi < 2; mi++)
                #pragma unroll
                for (int ni = 0; ni < 4; ni++)
                    mma_bf16(sf[mi][ni], qa[mi], kb0[ni]);
        }

        #pragma unroll
        for (int mi = 0; mi < 2; mi++) {
            const int r0 = R + mi * 16 + qr;
            const int* sp0 = spd + ((size_t)b2 * 512 + r0) * 512;
            const int* sp1 = sp0 + 8 * 512;
            #pragma unroll
            for (int ni = 0; ni < 4; ni++) {
                const int kk = KB + ni * 8 + qc2;
                int2 sd0 = *(const int2*)&sp0[kk];
                int2 sd1 = *(const int2*)&sp1[kk];
                float p0 = __expf(sf[mi][ni][0] + SB2[sd0.x + 1]);
                float p1 = __expf(sf[mi][ni][1] + SB2[sd0.y + 1]);
                float p2 = __expf(sf[mi][ni][2] + SB2[sd1.x + 1]);
                float p3 = __expf(sf[mi][ni][3] + SB2[sd1.y + 1]);
                rsum[mi][0] += p0 + p1;
                rsum[mi][1] += p2 + p3;
                sf[mi][ni][0] = p0; sf[mi][ni][1] = p1;
                sf[mi][ni][2] = p2; sf[mi][ni][3] = p3;
            }
        }

        #pragma unroll
        for (int t = 0; t < 2; t++) {
            uint32_t pa0[2][4], pa1[2][4];
            #pragma unroll
            for (int mi = 0; mi < 2; mi++) {
                float* sA = sf[mi][2 * t];
                float* sB = sf[mi][2 * t + 1];
                pa0[mi][0] = packbf(sA[0], sA[1]);
                pa0[mi][1] = packbf(sA[2], sA[3]);
                pa0[mi][2] = packbf(sB[0], sB[1]);
                pa0[mi][3] = packbf(sB[2], sB[3]);
                pa1[mi][0] = packbf_lo(sA[0], sA[1], pa0[mi][0]);
                pa1[mi][1] = packbf_lo(sA[2], sA[3], pa0[mi][1]);
                pa1[mi][2] = packbf_lo(sB[0], sB[1], pa0[mi][2]);
                pa1[mi][3] = packbf_lo(sB[2], sB[3], pa0[mi][3]);
            }
            uint32_t vb0[4][2], vb1[4][2];
            #pragma unroll
            for (int ni = 0; ni < 4; ni++)
                ldmatrix_x2(vb0[ni], &V0t[(ni * 8 + blr) * VPIT + KB + t * 16 + blc]);
            #pragma unroll
            for (int ni = 0; ni < 4; ni++)
                ldmatrix_x2(vb1[ni], &V1t[(ni * 8 + blr) * VPIT + KB + t * 16 + blc]);
            #pragma unroll
            for (int mi = 0; mi < 2; mi++)
                #pragma unroll
                for (int ni = 0; ni < 4; ni++) {
                    mma_bf16(o[mi][ni], pa0[mi], vb0[ni]);
                    mma_bf16(o[mi][ni], pa1[mi], vb0[ni]);
                    mma_bf16(o[mi][ni], pa0[mi], vb1[ni]);
                }
        }
    }

    #pragma unroll
    for (int mi = 0; mi < 2; mi++) {
        float s0 = rsum[mi][0];
        s0 += __shfl_xor_sync(0xffffffffu, s0, 1);
        s0 += __shfl_xor_sync(0xffffffffu, s0, 2);
        float s1 = rsum[mi][1];
        s1 += __shfl_xor_sync(0xffffffffu, s1, 1);
        s1 += __shfl_xor_sync(0xffffffffu, s1, 2);
        float inv0 = 1.f / s0;
        float inv1 = 1.f / s1;
        const size_t gr0 = (size_t)b * 512 + R + mi * 16 + qr;
        #pragma unroll
        for (int ni = 0; ni < 4; ni++) {
            const int dh = qcol + ni * 8 + qc2;
            float v00 = o[mi][ni][0] * inv0;
            float v01 = o[mi][ni][1] * inv0;
            float v10 = o[mi][ni][2] * inv1;
            float v11 = o[mi][ni][3] * inv1;
            uint32_t hi0 = packbf(v00, v01);
            uint32_t lo0 = packbf_lo(v00, v01, hi0);
            uint32_t hi1 = packbf(v10, v11);
            uint32_t lo1 = packbf_lo(v10, v11, hi1);
            *(uint32_t*)&U0[gr0 * 256 + dh]       = hi0;
            *(uint32_t*)&U1[gr0 * 256 + dh]       = lo0;
            *(uint32_t*)&U0[(gr0 + 8) * 256 + dh] = hi1;
            *(uint32_t*)&U1[(gr0 + 8) * 256 + dh] = lo1;
        }
    }
}

// ---------------------------------------------------------------------------
// Launch. Slot 4 = first gemm_mma (ncu window).
// ---------------------------------------------------------------------------
extern "C" void kernel_launch(void* const* d_in, const int* in_sizes, int n_in,
                              void* d_out, int out_size) {
    const float* x       = (const float*)d_in[0];
    const int*   adj     = (const int*)  d_in[1];
    const int*   spd     = (const int*)  d_in[2];
    const float* W_first = (const float*)d_in[3];
    const float* b_first = (const float*)d_in[4];
    const float* bn1_g   = (const float*)d_in[5];
    const float* bn1_b   = (const float*)d_in[6];
    const float* deg_emb = (const float*)d_in[7];
    const float* spd_emb = (const float*)d_in[8];
    const float* Wqkv    = (const float*)d_in[9];
    const float* bqkv    = (const float*)d_in[10];
    const float* Wo      = (const float*)d_in[11];
    const float* bo      = (const float*)d_in[12];
    const float* ln1_g   = (const float*)d_in[13];
    const float* ln1_b   = (const float*)d_in[14];
    const float* W1      = (const float*)d_in[15];
    const float* b1      = (const float*)d_in[16];
    const float* W2      = (const float*)d_in[17];
    const float* b2      = (const float*)d_in[18];
    const float* ln2_g   = (const float*)d_in[19];
    const float* ln2_b   = (const float*)d_in[20];
    const float* W_in    = (const float*)d_in[21];
    const float* b_in    = (const float*)d_in[22];
    const float* bn2_g   = (const float*)d_in[23];
    const float* bn2_b   = (const float*)d_in[24];
    float* out = (float*)d_out;

    float *pH, *pT1;
    __nv_bfloat16 *pH0, *pH1, *pU0, *pU1, *pW0, *pW1, *pS0, *pS1;
    cudaGetSymbolAddress((void**)&pH,  g_h);
    cudaGetSymbolAddress((void**)&pT1, g_t1);
    cudaGetSymbolAddress((void**)&pH0, g_h0);
    cudaGetSymbolAddress((void**)&pH1, g_h1);
    cudaGetSymbolAddress((void**)&pU0, g_u0);
    cudaGetSymbolAddress((void**)&pU1, g_u1);
    cudaGetSymbolAddress((void**)&pW0, g_w0);
    cudaGetSymbolAddress((void**)&pW1, g_w1);
    cudaGetSymbolAddress((void**)&pS0, g_s0);
    cudaGetSymbolAddress((void**)&pS1, g_s1);

    cudaFuncSetAttribute(attn_fa,
                         cudaFuncAttributeMaxDynamicSharedMemorySize, ATTN_SMEM);
    cudaFuncSetAttribute(gemm_mma<0>,
                         cudaFuncAttributeMaxDynamicSharedMemorySize, GEMM_SMEM);
    cudaFuncSetAttribute(gemm_mma<1>,
                         cudaFuncAttributeMaxDynamicSharedMemorySize, GEMM_SMEM);
    cudaFuncSetAttribute(gemm_mma<2>,
                         cudaFuncAttributeMaxDynamicSharedMemorySize, GEMM_SMEM);
    cudaFuncSetAttribute(gemm_mma<3>,
                         cudaFuncAttributeMaxDynamicSharedMemorySize, GEMM_SMEM);

    const dim3 g1(128, 1), g3(128, 3);

    split_kernel<<<M_ * 64 / 256, 256>>>(x, pH0, pH1, M_ * 64);             // 1
    split5_kernel<<<512, 256>>>(W_first, Wo, W1, W2, W_in, pW0, pW1);       // 2
    deg_kernel<<<dim3(4, 32), 128>>>(adj);                                  // 3
    gemm_mma<0><<<g1, 256, GEMM_SMEM>>>(pH0, pH1, pW0 + OFF_FIRST,          // 4
                                        pW1 + OFF_FIRST, b_first, pT1,
                                        nullptr, nullptr, 256, nullptr, nullptr);
    split_kernel<<<384, 256>>>(Wqkv, pW0 + OFF_QKV, pW1 + OFF_QKV, 98304);  // 5
    finalize_bn_kernel<<<1, 256>>>(bn1_g, bn1_b);
    bn_deg_kernel<<<M_ * 64 / 256, 256>>>(pT1, deg_emb);

    for (int l = 0; l < L_; l++) {
        gemm_mma<2><<<g3, 256, GEMM_SMEM>>>(pH0, pH1,
            pW0 + OFF_QKV + (size_t)l * 196608, pW1 + OFF_QKV + (size_t)l * 196608,
            bqkv + l * 768, nullptr, pS0, pS1, 768, nullptr, nullptr);
        attn_fa<<<B_ * H_, 512, ATTN_SMEM>>>(pS0, pS1, spd, spd_emb, pU0, pU1);
        gemm_mma<3><<<g1, 256, GEMM_SMEM>>>(pU0, pU1,
            pW0 + OFF_WO + (size_t)l * 65536, pW1 + OFF_WO + (size_t)l * 65536,
            bo + l * 256, pH, pH0, pH1, 256, ln1_g + l * 256, ln1_b + l * 256);
        gemm_mma<1><<<g1, 256, GEMM_SMEM>>>(pH0, pH1,
            pW0 + OFF_W1 + (size_t)l * 65536, pW1 + OFF_W1 + (size_t)l * 65536,
            b1 + l * 256, nullptr, pU0, pU1, 256, nullptr, nullptr);
        gemm_mma<3><<<g1, 256, GEMM_SMEM>>>(pU0, pU1,
            pW0 + OFF_W2 + (size_t)l * 65536, pW1 + OFF_W2 + (size_t)l * 65536,
            b2 + l * 256, pH, pH0, pH1, 256, ln2_g + l * 256, ln2_b + l * 256);
    }

    gemm_mma<0><<<g1, 256, GEMM_SMEM>>>(pH0, pH1, pW0 + OFF_WIN, pW1 + OFF_WIN,
                                        b_in, pT1, nullptr, nullptr, 256,
                                        nullptr, nullptr);
    finalize_bn_kernel<<<1, 256>>>(bn2_g, bn2_b);
    bn_out_kernel<<<M_ * 64 / 256, 256>>>(pT1, out);
}

// round 16
// speedup vs baseline: 1.4963x; 1.0218x over previous
#include <cuda_runtime.h>
#include <cuda_bf16.h>
#include <math.h>
#include <stdint.h>

// ---------------------------------------------------------------------------
// Graphormer forward: B=32, N=512, D=256, H=8, DH=32, L=2
// GEMMs: mma.sync bf16 split-3-term.
//   - 128x128 tile, 2 CTA/SM (EPI 0/1/2: colstats / relu-split / qkv-split)
//   - 128x256 tile, 1 CTA/SM (EPI 3: residual + fused LayerNorm)
// Attention: FA-style register HMMA, one (b,h) per CTA, 512 threads
// ---------------------------------------------------------------------------
#define B_   32
#define N_   512
#define D_   256
#define H_   8
#define DH_  32
#define L_   2
#define M_   (B_ * N_)
#define EPS_ 1e-5f

typedef unsigned long long u64;

// ---------------- scratch ----------------
__device__ float          g_h [M_ * D_];
__device__ float          g_t1[M_ * D_];
__device__ __nv_bfloat16  g_h0[M_ * D_];
__device__ __nv_bfloat16  g_h1[M_ * D_];
__device__ __nv_bfloat16  g_u0[M_ * D_];
__device__ __nv_bfloat16  g_u1[M_ * D_];
__device__ __nv_bfloat16  g_s0[M_ * 3 * D_];
__device__ __nv_bfloat16  g_s1[M_ * 3 * D_];
__device__ __nv_bfloat16  g_w0[917504];
__device__ __nv_bfloat16  g_w1[917504];
__device__ int            g_deg[M_];
__device__ float          g_sum[D_], g_sqsum[D_], g_scale[D_], g_shift[D_];

#define OFF_FIRST 0
#define OFF_QKV   65536
#define OFF_WO    458752
#define OFF_W1    589824
#define OFF_W2    720896
#define OFF_WIN   851968

// ---------------------------------------------------------------------------
// mma.sync / ldmatrix / cp.async helpers
// ---------------------------------------------------------------------------
__device__ __forceinline__ void mma_bf16(float* d, const uint32_t* a,
                                         const uint32_t* b) {
    asm volatile(
        "mma.sync.aligned.m16n8k16.row.col.f32.bf16.bf16.f32 "
        "{%0,%1,%2,%3}, {%4,%5,%6,%7}, {%8,%9}, {%0,%1,%2,%3};"
        : "+f"(d[0]), "+f"(d[1]), "+f"(d[2]), "+f"(d[3])
        : "r"(a[0]), "r"(a[1]), "r"(a[2]), "r"(a[3]), "r"(b[0]), "r"(b[1]));
}
__device__ __forceinline__ void ldmatrix_x4(uint32_t* r, const void* p) {
    uint32_t addr = (uint32_t)__cvta_generic_to_shared(p);
    asm volatile("ldmatrix.sync.aligned.m8n8.x4.shared.b16 {%0,%1,%2,%3}, [%4];"
                 : "=r"(r[0]), "=r"(r[1]), "=r"(r[2]), "=r"(r[3]) : "r"(addr));
}
__device__ __forceinline__ void ldmatrix_x2(uint32_t* r, const void* p) {
    uint32_t addr = (uint32_t)__cvta_generic_to_shared(p);
    asm volatile("ldmatrix.sync.aligned.m8n8.x2.shared.b16 {%0,%1}, [%2];"
                 : "=r"(r[0]), "=r"(r[1]) : "r"(addr));
}
__device__ __forceinline__ void cp16(void* smem, const void* gmem) {
    uint32_t s = (uint32_t)__cvta_generic_to_shared(smem);
    asm volatile("cp.async.cg.shared.global [%0], [%1], 16;"
                 :: "r"(s), "l"(gmem));
}
#define CP_COMMIT() asm volatile("cp.async.commit_group;" ::: "memory")
#define CP_WAIT1()  asm volatile("cp.async.wait_group 1;" ::: "memory")
#define CP_WAIT0()  asm volatile("cp.async.wait_group 0;" ::: "memory")

__device__ __forceinline__ uint32_t packbf(float a, float b) {
    __nv_bfloat162 h;
    h.x = __float2bfloat16(a);
    h.y = __float2bfloat16(b);
    return *(uint32_t*)&h;
}
__device__ __forceinline__ uint32_t packbf_lo(float a, float b, uint32_t hi) {
    __nv_bfloat162 h = *(__nv_bfloat162*)&hi;
    return packbf(a - __bfloat162float(h.x), b - __bfloat162float(h.y));
}

// ---------------------------------------------------------------------------
// bf16 split helpers
// ---------------------------------------------------------------------------
__device__ __forceinline__ void split_store(__nv_bfloat16* p0, __nv_bfloat16* p1,
                                            float v) {
    __nv_bfloat16 b0 = __float2bfloat16(v);
    *p0 = b0;
    *p1 = __float2bfloat16(v - __bfloat162float(b0));
}

__device__ __forceinline__ void split4(const float* src,
                                       __nv_bfloat16* d0,
                                       __nv_bfloat16* d1, int i) {
    float4 v = ((const float4*)src)[i];
    __nv_bfloat162 h0a, h0b, h1a, h1b;
    h0a.x = __float2bfloat16(v.x);
    h0a.y = __float2bfloat16(v.y);
    h0b.x = __float2bfloat16(v.z);
    h0b.y = __float2bfloat16(v.w);
    h1a.x = __float2bfloat16(v.x - __bfloat162float(h0a.x));
    h1a.y = __float2bfloat16(v.y - __bfloat162float(h0a.y));
    h1b.x = __float2bfloat16(v.z - __bfloat162float(h0b.x));
    h1b.y = __float2bfloat16(v.w - __bfloat162float(h0b.y));
    ((__nv_bfloat162*)d0)[i * 2 + 0] = h0a;
    ((__nv_bfloat162*)d0)[i * 2 + 1] = h0b;
    ((__nv_bfloat162*)d1)[i * 2 + 0] = h1a;
    ((__nv_bfloat162*)d1)[i * 2 + 1] = h1b;
}

__global__ void split_kernel(const float* __restrict__ src,
                             __nv_bfloat16* __restrict__ d0,
                             __nv_bfloat16* __restrict__ d1, int n4) {
    int i = blockIdx.x * 256 + threadIdx.x;
    if (i >= n4) return;
    split4(src, d0, d1, i);
}

__global__ void split5_kernel(const float* __restrict__ Wf,
                              const float* __restrict__ Wo,
                              const float* __restrict__ W1f,
                              const float* __restrict__ W2f,
                              const float* __restrict__ Win,
                              __nv_bfloat16* __restrict__ w0,
                              __nv_bfloat16* __restrict__ w1) {
    int b = blockIdx.x;
    if (b == 0) {
        g_sum[threadIdx.x] = 0.f;
        g_sqsum[threadIdx.x] = 0.f;
    }
    const float* src; int base, rel;
    if (b < 64)       { src = Wf;  base = OFF_FIRST; rel = b; }
    else if (b < 192) { src = Wo;  base = OFF_WO;    rel = b - 64; }
    else if (b < 320) { src = W1f; base = OFF_W1;    rel = b - 192; }
    else if (b < 448) { src = W2f; base = OFF_W2;    rel = b - 320; }
    else              { src = Win; base = OFF_WIN;   rel = b - 448; }
    int i = rel * 256 + threadIdx.x;
    split4(src, w0 + base, w1 + base, i);
}

// ---------------------------------------------------------------------------
// GEMM variant A: 128x128 tile, 256 thr (8 warps 2x4, warp tile 64x32),
// BK=32, 2-stage cp.async, 2 CTAs/SM (R8 config, tensor ~41%).
// EPI 0: fp32 out + colstats. EPI 1: relu + splits. EPI 2: qkv splits
// (Q cols [0,256) scaled by 1/sqrt(32)).
// ---------------------------------------------------------------------------
#define PADK    40
#define T128_B  (128 * PADK * 2)          // 10240
#define B128_B  (4 * T128_B)              // 40960
#define G128_SMEM (512 + 2 * B128_B)      // 82432 -> 2 CTAs/SM

__device__ __forceinline__ void load_tiles128(
    char* buf, const __nv_bfloat16* A0, const __nv_bfloat16* A1,
    const __nv_bfloat16* W0, const __nv_bfloat16* W1,
    int bm, int bn, int k0, int tid)
{
    const __nv_bfloat16* srcs[4] = {A0, A1, W0, W1};
    const int r0s[4] = {bm, bm, bn, bn};
    #pragma unroll
    for (int t = 0; t < 4; t++) {
        char* dst = buf + t * T128_B;
        const __nv_bfloat16* src = srcs[t];
        const int r0 = r0s[t];
        #pragma unroll
        for (int i = 0; i < 2; i++) {
            int id  = tid + i * 256;
            int row = id >> 2;
            int cb  = id & 3;
            cp16(dst + row * 80 + cb * 16,
                 &src[(size_t)(r0 + row) * 256 + k0 + cb * 8]);
        }
    }
}

template <int EPI>
__global__ __launch_bounds__(256, 2) void gemm128(
    const __nv_bfloat16* __restrict__ A0, const __nv_bfloat16* __restrict__ A1,
    const __nv_bfloat16* __restrict__ W0, const __nv_bfloat16* __restrict__ W1,
    const float* __restrict__ bias, float* __restrict__ Cf,
    __nv_bfloat16* __restrict__ U0, __nv_bfloat16* __restrict__ U1, int Nc)
{
    extern __shared__ char smem[];
    float* bsm = (float*)smem;

    const int tid  = threadIdx.x;
    const int wid  = tid >> 5;
    const int lane = tid & 31;
    const int bm   = blockIdx.x * 128;
    const int bn   = blockIdx.y * 128;
    const int wm   = wid >> 2;
    const int wn   = wid & 3;

    if (tid < 128) bsm[tid] = bias[bn + tid];

    float acc[4][4][4];
    #pragma unroll
    for (int mi = 0; mi < 4; mi++)
        #pragma unroll
        for (int ni = 0; ni < 4; ni++)
            #pragma unroll
            for (int k = 0; k < 4; k++) acc[mi][ni][k] = 0.f;

    const int alr = lane & 15;
    const int alc = (lane >> 4) * 8;
    const int blr = lane & 7;
    const int blc = ((lane >> 3) & 1) * 8;

    load_tiles128(smem + 512, A0, A1, W0, W1, bm, bn, 0, tid);
    CP_COMMIT();

    #pragma unroll
    for (int c = 0; c < 8; c++) {
        if (c < 7) {
            load_tiles128(smem + 512 + ((c + 1) & 1) * B128_B,
                          A0, A1, W0, W1, bm, bn, (c + 1) * 32, tid);
            CP_COMMIT();
            CP_WAIT1();
        } else {
            CP_WAIT0();
        }
        __syncthreads();

        char* buf = smem + 512 + (c & 1) * B128_B;
        __nv_bfloat16* A0s = (__nv_bfloat16*)(buf);
        __nv_bfloat16* A1s = (__nv_bfloat16*)(buf + T128_B);
        __nv_bfloat16* W0s = (__nv_bfloat16*)(buf + 2 * T128_B);
        __nv_bfloat16* W1s = (__nv_bfloat16*)(buf + 3 * T128_B);

        #pragma unroll
        for (int ks = 0; ks < 32; ks += 16) {
            uint32_t af[4][4], b0f[4][2], b1f[4][2];
            #pragma unroll
            for (int mi = 0; mi < 4; mi++)
                ldmatrix_x4(af[mi],
                    &A0s[(wm * 64 + mi * 16 + alr) * PADK + ks + alc]);
            #pragma unroll
            for (int ni = 0; ni < 4; ni++)
                ldmatrix_x2(b0f[ni],
                    &W0s[(wn * 32 + ni * 8 + blr) * PADK + ks + blc]);
            #pragma unroll
            for (int ni = 0; ni < 4; ni++)
                ldmatrix_x2(b1f[ni],
                    &W1s[(wn * 32 + ni * 8 + blr) * PADK + ks + blc]);

            #pragma unroll
            for (int mi = 0; mi < 4; mi++)
                #pragma unroll
                for (int ni = 0; ni < 4; ni++) {
                    mma_bf16(acc[mi][ni], af[mi], b0f[ni]);
                    mma_bf16(acc[mi][ni], af[mi], b1f[ni]);
                }
            #pragma unroll
            for (int mi = 0; mi < 4; mi++)
                ldmatrix_x4(af[mi],
                    &A1s[(wm * 64 + mi * 16 + alr) * PADK + ks + alc]);
            #pragma unroll
            for (int mi = 0; mi < 4; mi++)
                #pragma unroll
                for (int ni = 0; ni < 4; ni++)
                    mma_bf16(acc[mi][ni], af[mi], b0f[ni]);
        }
        __syncthreads();
    }

    const int qr  = lane >> 2;
    const int qc2 = (lane & 3) * 2;

    if (EPI == 0) {
        #pragma unroll
        for (int ni = 0; ni < 4; ni++) {
            const int cl = wn * 32 + ni * 8 + qc2;
            const int gc = bn + cl;
            float cs0 = 0.f, cs1 = 0.f, cq0 = 0.f, cq1 = 0.f;
            #pragma unroll
            for (int mi = 0; mi < 4; mi++) {
                const int r0 = bm + wm * 64 + mi * 16 + qr;
                float v00 = acc[mi][ni][0] + bsm[cl];
                float v01 = acc[mi][ni][1] + bsm[cl + 1];
                float v10 = acc[mi][ni][2] + bsm[cl];
                float v11 = acc[mi][ni][3] + bsm[cl + 1];
                *(float2*)&Cf[(size_t)r0 * Nc + gc]       = make_float2(v00, v01);
                *(float2*)&Cf[(size_t)(r0 + 8) * Nc + gc] = make_float2(v10, v11);
                cs0 += v00 + v10; cs1 += v01 + v11;
                cq0 += v00 * v00 + v10 * v10;
                cq1 += v01 * v01 + v11 * v11;
            }
            #pragma unroll
            for (int off = 4; off <= 16; off <<= 1) {
                cs0 += __shfl_xor_sync(0xffffffffu, cs0, off);
                cs1 += __shfl_xor_sync(0xffffffffu, cs1, off);
                cq0 += __shfl_xor_sync(0xffffffffu, cq0, off);
                cq1 += __shfl_xor_sync(0xffffffffu, cq1, off);
            }
            if (qr == 0) {
                atomicAdd(&g_sum[gc],       cs0);
                atomicAdd(&g_sum[gc + 1],   cs1);
                atomicAdd(&g_sqsum[gc],     cq0);
                atomicAdd(&g_sqsum[gc + 1], cq1);
            }
        }
    } else {
        const float esc = (EPI == 2 && bn < 256) ? 0.17677669529663687f : 1.0f;
        #pragma unroll
        for (int mi = 0; mi < 4; mi++) {
            #pragma unroll
            for (int ni = 0; ni < 4; ni++) {
                const int cl = wn * 32 + ni * 8 + qc2;
                const int gc = bn + cl;
                const int r0 = bm + wm * 64 + mi * 16 + qr;
                float v00 = acc[mi][ni][0] + bsm[cl];
                float v01 = acc[mi][ni][1] + bsm[cl + 1];
                float v10 = acc[mi][ni][2] + bsm[cl];
                float v11 = acc[mi][ni][3] + bsm[cl + 1];
                if (EPI == 1) {
                    v00 = fmaxf(v00, 0.f); v01 = fmaxf(v01, 0.f);
                    v10 = fmaxf(v10, 0.f); v11 = fmaxf(v11, 0.f);
                } else {
                    v00 *= esc; v01 *= esc; v10 *= esc; v11 *= esc;
                }
                uint32_t hi0 = packbf(v00, v01);
                uint32_t lo0 = packbf_lo(v00, v01, hi0);
                uint32_t hi1 = packbf(v10, v11);
                uint32_t lo1 = packbf_lo(v10, v11, hi1);
                *(uint32_t*)&U0[(size_t)r0 * Nc + gc]       = hi0;
                *(uint32_t*)&U1[(size_t)r0 * Nc + gc]       = lo0;
                *(uint32_t*)&U0[(size_t)(r0 + 8) * Nc + gc] = hi1;
                *(uint32_t*)&U1[(size_t)(r0 + 8) * Nc + gc] = lo1;
            }
        }
    }
}

// ---------------------------------------------------------------------------
// GEMM variant B: 128x256 tile, 256 thr (warp tile 64x64), fused
// residual + LayerNorm epilogue (EPI 3 only). R11/R15 config.
// ---------------------------------------------------------------------------
#define A_TILE_B (128 * PADK * 2)
#define W_TILE_B (256 * PADK * 2)
#define STAGE_B  (2 * A_TILE_B + 2 * W_TILE_B)   // 61440
#define HDR_B    5120
#define G256_SMEM (HDR_B + 2 * STAGE_B)          // 128000

__device__ __forceinline__ void load_stage256(
    char* buf, const __nv_bfloat16* A0, const __nv_bfloat16* A1,
    const __nv_bfloat16* W0, const __nv_bfloat16* W1,
    int bm, int bn, int k0, int tid)
{
    #pragma unroll
    for (int i = 0; i < 4; i++) {
        int id  = tid + i * 256;
        int s   = id >> 9;
        int row = (id >> 2) & 127;
        int cb  = id & 3;
        const __nv_bfloat16* src = s ? A1 : A0;
        cp16(buf + s * A_TILE_B + row * 80 + cb * 16,
             &src[(size_t)(bm + row) * 256 + k0 + cb * 8]);
    }
    char* wb = buf + 2 * A_TILE_B;
    #pragma unroll
    for (int i = 0; i < 8; i++) {
        int id  = tid + i * 256;
        int s   = id >> 10;
        int row = (id >> 2) & 255;
        int cb  = id & 3;
        const __nv_bfloat16* src = s ? W1 : W0;
        cp16(wb + s * W_TILE_B + row * 80 + cb * 16,
             &src[(size_t)(bn + row) * 256 + k0 + cb * 8]);
    }
}

__global__ __launch_bounds__(256) void gemm256_ln(
    const __nv_bfloat16* __restrict__ A0, const __nv_bfloat16* __restrict__ A1,
    const __nv_bfloat16* __restrict__ W0, const __nv_bfloat16* __restrict__ W1,
    const float* __restrict__ bias, float* __restrict__ Cf,
    __nv_bfloat16* __restrict__ U0, __nv_bfloat16* __restrict__ U1,
    const float* __restrict__ gamma, const float* __restrict__ beta)
{
    extern __shared__ char smem[];
    float* bsm  = (float*)smem;                 // [256]
    float* psum = (float*)(smem + 1024);        // [128][4]
    float* psq  = (float*)(smem + 3072);        // [128][4]

    const int tid  = threadIdx.x;
    const int wid  = tid >> 5;
    const int lane = tid & 31;
    const int bm   = blockIdx.x * 128;
    const int bn   = 0;
    const int wm   = wid >> 2;
    const int wn   = wid & 3;

    bsm[tid] = bias[tid];

    float acc[4][8][4];
    #pragma unroll
    for (int mi = 0; mi < 4; mi++)
        #pragma unroll
        for (int ni = 0; ni < 8; ni++)
            #pragma unroll
            for (int k = 0; k < 4; k++) acc[mi][ni][k] = 0.f;

    const int alr = lane & 15;
    const int alc = (lane >> 4) * 8;
    const int blr = lane & 7;
    const int blc = ((lane >> 3) & 1) * 8;

    load_stage256(smem + HDR_B, A0, A1, W0, W1, bm, bn, 0, tid);
    CP_COMMIT();

    #pragma unroll
    for (int c = 0; c < 8; c++) {
        if (c < 7) {
            load_stage256(smem + HDR_B + ((c + 1) & 1) * STAGE_B,
                          A0, A1, W0, W1, bm, bn, (c + 1) * 32, tid);
            CP_COMMIT();
            CP_WAIT1();
        } else {
            CP_WAIT0();
        }
        __syncthreads();

        char* buf = smem + HDR_B + (c & 1) * STAGE_B;
        __nv_bfloat16* A0s = (__nv_bfloat16*)(buf);
        __nv_bfloat16* A1s = (__nv_bfloat16*)(buf + A_TILE_B);
        __nv_bfloat16* W0s = (__nv_bfloat16*)(buf + 2 * A_TILE_B);
        __nv_bfloat16* W1s = (__nv_bfloat16*)(buf + 2 * A_TILE_B + W_TILE_B);

        #pragma unroll
        for (int ks = 0; ks < 32; ks += 16) {
            uint32_t af[4][4], w0f[8][2], w1f[8][2];
            #pragma unroll
            for (int mi = 0; mi < 4; mi++)
                ldmatrix_x4(af[mi],
                    &A0s[(wm * 64 + mi * 16 + alr) * PADK + ks + alc]);
            #pragma unroll
            for (int ni = 0; ni < 8; ni++)
                ldmatrix_x2(w0f[ni],
                    &W0s[(wn * 64 + ni * 8 + blr) * PADK + ks + blc]);
            #pragma unroll
            for (int ni = 0; ni < 8; ni++)
                ldmatrix_x2(w1f[ni],
                    &W1s[(wn * 64 + ni * 8 + blr) * PADK + ks + blc]);

            #pragma unroll
            for (int mi = 0; mi < 4; mi++)
                #pragma unroll
                for (int ni = 0; ni < 8; ni++) {
                    mma_bf16(acc[mi][ni], af[mi], w0f[ni]);
                    mma_bf16(acc[mi][ni], af[mi], w1f[ni]);
                }
            #pragma unroll
            for (int mi = 0; mi < 4; mi++)
                ldmatrix_x4(af[mi],
                    &A1s[(wm * 64 + mi * 16 + alr) * PADK + ks + alc]);
            #pragma unroll
            for (int mi = 0; mi < 4; mi++)
                #pragma unroll
                for (int ni = 0; ni < 8; ni++)
                    mma_bf16(acc[mi][ni], af[mi], w0f[ni]);
        }
        __syncthreads();
    }

    const int qr  = lane >> 2;
    const int qc2 = (lane & 3) * 2;

    #pragma unroll
    for (int mi = 0; mi < 4; mi++) {
        const int lr0 = wm * 64 + mi * 16 + qr;
        const int gr0 = bm + lr0;
        float sA = 0.f, qA = 0.f, sB = 0.f, qB = 0.f;
        #pragma unroll
        for (int ni = 0; ni < 8; ni++) {
            const int cl = wn * 64 + ni * 8 + qc2;
            float2 h0v = *(float2*)&Cf[(size_t)gr0 * 256 + cl];
            float2 h1v = *(float2*)&Cf[(size_t)(gr0 + 8) * 256 + cl];
            float v00 = acc[mi][ni][0] + bsm[cl]     + h0v.x;
            float v01 = acc[mi][ni][1] + bsm[cl + 1] + h0v.y;
            float v10 = acc[mi][ni][2] + bsm[cl]     + h1v.x;
            float v11 = acc[mi][ni][3] + bsm[cl + 1] + h1v.y;
            acc[mi][ni][0] = v00; acc[mi][ni][1] = v01;
            acc[mi][ni][2] = v10; acc[mi][ni][3] = v11;
            sA += v00 + v01; qA += v00 * v00 + v01 * v01;
            sB += v10 + v11; qB += v10 * v10 + v11 * v11;
        }
        sA += __shfl_xor_sync(0xffffffffu, sA, 1);
        sA += __shfl_xor_sync(0xffffffffu, sA, 2);
        qA += __shfl_xor_sync(0xffffffffu, qA, 1);
        qA += __shfl_xor_sync(0xffffffffu, qA, 2);
        sB += __shfl_xor_sync(0xffffffffu, sB, 1);
        sB += __shfl_xor_sync(0xffffffffu, sB, 2);
        qB += __shfl_xor_sync(0xffffffffu, qB, 1);
        qB += __shfl_xor_sync(0xffffffffu, qB, 2);
        if ((lane & 3) == 0) {
            psum[lr0 * 4 + wn]       = sA;
            psq [lr0 * 4 + wn]       = qA;
            psum[(lr0 + 8) * 4 + wn] = sB;
            psq [(lr0 + 8) * 4 + wn] = qB;
        }
    }
    __syncthreads();
    #pragma unroll
    for (int mi = 0; mi < 4; mi++) {
        const int lr0 = wm * 64 + mi * 16 + qr;
        const int gr0 = bm + lr0;
        float s0 = psum[lr0 * 4] + psum[lr0 * 4 + 1]
                 + psum[lr0 * 4 + 2] + psum[lr0 * 4 + 3];
        float q0 = psq[lr0 * 4] + psq[lr0 * 4 + 1]
                 + psq[lr0 * 4 + 2] + psq[lr0 * 4 + 3];
        float s1 = psum[(lr0 + 8) * 4] + psum[(lr0 + 8) * 4 + 1]
                 + psum[(lr0 + 8) * 4 + 2] + psum[(lr0 + 8) * 4 + 3];
        float q1 = psq[(lr0 + 8) * 4] + psq[(lr0 + 8) * 4 + 1]
                 + psq[(lr0 + 8) * 4 + 2] + psq[(lr0 + 8) * 4 + 3];
        float m0 = s0 * (1.f / 256.f);
        float m1 = s1 * (1.f / 256.f);
        float r0v = rsqrtf(q0 * (1.f / 256.f) - m0 * m0 + EPS_);
        float r1v = rsqrtf(q1 * (1.f / 256.f) - m1 * m1 + EPS_);
        #pragma unroll
        for (int ni = 0; ni < 8; ni++) {
            const int cl = wn * 64 + ni * 8 + qc2;
            float g0 = __ldg(&gamma[cl]), g1 = __ldg(&gamma[cl + 1]);
            float e0 = __ldg(&beta[cl]),  e1 = __ldg(&beta[cl + 1]);
            float v00 = (acc[mi][ni][0] - m0) * r0v * g0 + e0;
            float v01 = (acc[mi][ni][1] - m0) * r0v * g1 + e1;
            float v10 = (acc[mi][ni][2] - m1) * r1v * g0 + e0;
            float v11 = (acc[mi][ni][3] - m1) * r1v * g1 + e1;
            *(float2*)&Cf[(size_t)gr0 * 256 + cl]       = make_float2(v00, v01);
            *(float2*)&Cf[(size_t)(gr0 + 8) * 256 + cl] = make_float2(v10, v11);
            uint32_t hi0 = packbf(v00, v01);
            uint32_t lo0 = packbf_lo(v00, v01, hi0);
            uint32_t hi1 = packbf(v10, v11);
            uint32_t lo1 = packbf_lo(v10, v11, hi1);
            *(uint32_t*)&U0[(size_t)gr0 * 256 + cl]       = hi0;
            *(uint32_t*)&U1[(size_t)gr0 * 256 + cl]       = lo0;
            *(uint32_t*)&U0[(size_t)(gr0 + 8) * 256 + cl] = hi1;
            *(uint32_t*)&U1[(size_t)(gr0 + 8) * 256 + cl] = lo1;
        }
    }
}

// ---------------------------------------------------------------------------
// BatchNorm / misc helpers
// ---------------------------------------------------------------------------
__global__ void finalize_bn_kernel(const float* __restrict__ g,
                                   const float* __restrict__ b) {
    int c = threadIdx.x;
    float m  = g_sum[c]   * (1.f / (float)M_);
    float v  = g_sqsum[c] * (1.f / (float)M_) - m * m;
    float sc = g[c] * rsqrtf(v + EPS_);
    g_scale[c] = sc;
    g_shift[c] = b[c] - m * sc;
    g_sum[c] = 0.f; g_sqsum[c] = 0.f;
}

__global__ void deg_kernel(const int* __restrict__ adj) {
    int b = blockIdx.y;
    int n = blockIdx.x * 128 + threadIdx.x;
    const int* p = adj + (size_t)b * N_ * N_ + n;
    int s = 0;
    #pragma unroll 4
    for (int i = 0; i < N_; i++) s += (p[(size_t)i * N_] != 0);
    g_deg[b * N_ + n] = s;
}

__global__ void bn_deg_kernel(const float* __restrict__ A,
                              const float* __restrict__ deg_emb) {
    int idx = blockIdx.x * 256 + threadIdx.x;
    int row = idx >> 6;
    int c   = (idx & 63) << 2;
    float4 a = *(const float4*)&A[(size_t)row * D_ + c];
    const float* de = &deg_emb[(size_t)g_deg[row] * D_ + c];
    float y[4] = {a.x, a.y, a.z, a.w};
    float4 o; float* op = (float*)&o;
    #pragma unroll
    for (int k = 0; k < 4; k++) {
        float t = y[k] * g_scale[c + k] + g_shift[c + k];
        t = t >= 0.f ? t : 0.01f * t;
        op[k] = t + de[k];
    }
    size_t base = (size_t)row * D_ + c;
    *(float4*)&g_h[base] = o;
    #pragma unroll
    for (int k = 0; k < 4; k++) split_store(&g_h0[base + k], &g_h1[base + k], op[k]);
}

__global__ void bn_out_kernel(const float* __restrict__ A,
                              float* __restrict__ out) {
    int idx = blockIdx.x * 256 + threadIdx.x;
    int row = idx >> 6;
    int c   = (idx & 63) << 2;
    float4 a = *(const float4*)&A[(size_t)row * D_ + c];
    float y[4] = {a.x, a.y, a.z, a.w};
    float4 o; float* op = (float*)&o;
    #pragma unroll
    for (int k = 0; k < 4; k++) {
        float t = y[k] * g_scale[c + k] + g_shift[c + k];
        op[k] = t >= 0.f ? t : 0.01f * t;
    }
    *(float4*)&out[(size_t)row * D_ + c] = o;
}

// ---------------------------------------------------------------------------
// FA-style HMMA attention: one (b,h) per CTA, 512 threads (16 warps,
// 32 query rows each). R15 config (best).
// ---------------------------------------------------------------------------
#define APIT 40
#define VPIT 520
#define SM_Q0  0
#define SM_Q1  40960
#define SM_K0  81920
#define SM_K1  122880
#define SM_VT0 163840
#define SM_VT1 197120
#define SM_LUT 230400
#define ATTN_SMEM 230912

__global__ __launch_bounds__(512, 1) void attn_fa(
    const __nv_bfloat16* __restrict__ gS0, const __nv_bfloat16* __restrict__ gS1,
    const int* __restrict__ spd, const float* __restrict__ spd_emb,
    __nv_bfloat16* __restrict__ U0, __nv_bfloat16* __restrict__ U1)
{
    extern __shared__ char smem[];
    __nv_bfloat16* Q0s = (__nv_bfloat16*)(smem + SM_Q0);
    __nv_bfloat16* Q1s = (__nv_bfloat16*)(smem + SM_Q1);
    __nv_bfloat16* K0s = (__nv_bfloat16*)(smem + SM_K0);
    __nv_bfloat16* K1s = (__nv_bfloat16*)(smem + SM_K1);
    __nv_bfloat16* V0t = (__nv_bfloat16*)(smem + SM_VT0);
    __nv_bfloat16* V1t = (__nv_bfloat16*)(smem + SM_VT1);
    float*         SB2 = (float*)(smem + SM_LUT);

    const int bh = blockIdx.x;
    const int b  = bh >> 3;
    const int hh = bh & 7;
    const int b2 = bh & 31;
    const int ei = bh >> 5;
    const int tid  = threadIdx.x;
    const int wid  = tid >> 5;
    const int lane = tid & 31;

    const size_t rowbase = (size_t)b * 512 * 768;
    const int qcol = hh * 32;

    #pragma unroll
    for (int t = 0; t < 4; t++) {
        int id  = tid + t * 512;
        int row = id >> 2;
        int cb  = (id & 3) * 8;
        size_t g = rowbase + (size_t)row * 768;
        cp16(&Q0s[row * APIT + cb], &gS0[g + qcol + cb]);
        cp16(&Q1s[row * APIT + cb], &gS1[g + qcol + cb]);
        cp16(&K0s[row * APIT + cb], &gS0[g + 256 + qcol + cb]);
        cp16(&K1s[row * APIT + cb], &gS1[g + 256 + qcol + cb]);
    }
    CP_COMMIT();

    for (int idx = tid; idx < 2048; idx += 512) {
        int k  = idx >> 2;
        int dc = (idx & 3) * 8;
        size_t g = rowbase + (size_t)k * 768 + 512 + qcol + dc;
        uint4 v0 = *(const uint4*)&gS0[g];
        uint4 v1 = *(const uint4*)&gS1[g];
        const __nv_bfloat16* e0 = (const __nv_bfloat16*)&v0;
        const __nv_bfloat16* e1 = (const __nv_bfloat16*)&v1;
        #pragma unroll
        for (int e = 0; e < 8; e++) {
            V0t[(dc + e) * VPIT + k] = e0[e];
            V1t[(dc + e) * VPIT + k] = e1[e];
        }
    }
    if (tid < 100) SB2[tid + 1] = spd_emb[tid * H_ + ei];
    if (tid == 100) SB2[0] = -1.0f;
    CP_WAIT0();
    __syncthreads();

    const int R   = wid * 32;
    const int alr = lane & 15;
    const int alc = (lane >> 4) * 8;
    const int blr = lane & 7;
    const int blc = ((lane >> 3) & 1) * 8;
    const int qr  = lane >> 2;
    const int qc2 = (lane & 3) * 2;

    float o[2][4][4];
    float rsum[2][2];
    #pragma unroll
    for (int mi = 0; mi < 2; mi++) {
        rsum[mi][0] = 0.f; rsum[mi][1] = 0.f;
        #pragma unroll
        for (int ni = 0; ni < 4; ni++)
            #pragma unroll
            for (int k = 0; k < 4; k++) o[mi][ni][k] = 0.f;
    }

    for (int ch = 0; ch < 16; ch++) {
        const int KB = ch * 32;

        float sf[2][4][4];
        #pragma unroll
        for (int mi = 0; mi < 2; mi++)
            #pragma unroll
            for (int ni = 0; ni < 4; ni++)
                #pragma unroll
                for (int k = 0; k < 4; k++) sf[mi][ni][k] = 0.f;

        #pragma unroll
        for (int ks = 0; ks < 32; ks += 16) {
            uint32_t qa[2][4], kb0[4][2], kb1[4][2];
            #pragma unroll
            for (int mi = 0; mi < 2; mi++)
                ldmatrix_x4(qa[mi], &Q0s[(R + mi * 16 + alr) * APIT + ks + alc]);
            #pragma unroll
            for (int ni = 0; ni < 4; ni++)
                ldmatrix_x2(kb0[ni], &K0s[(KB + ni * 8 + blr) * APIT + ks + blc]);
            #pragma unroll
            for (int ni = 0; ni < 4; ni++)
                ldmatrix_x2(kb1[ni], &K1s[(KB + ni * 8 + blr) * APIT + ks + blc]);
            #pragma unroll
            for (int mi = 0; mi < 2; mi++)
                #pragma unroll
                for (int ni = 0; ni < 4; ni++) {
                    mma_bf16(sf[mi][ni], qa[mi], kb0[ni]);
                    mma_bf16(sf[mi][ni], qa[mi], kb1[ni]);
                }
            #pragma unroll
            for (int mi = 0; mi < 2; mi++)
                ldmatrix_x4(qa[mi], &Q1s[(R + mi * 16 + alr) * APIT + ks + alc]);
            #pragma unroll
            for (int mi = 0; mi < 2; mi++)
                #pragma unroll
                for (int ni = 0; ni < 4; ni++)
                    mma_bf16(sf[mi][ni], qa[mi], kb0[ni]);
        }

        #pragma unroll
        for (int mi = 0; mi < 2; mi++) {
            const int r0 = R + mi * 16 + qr;
            const int* sp0 = spd + ((size_t)b2 * 512 + r0) * 512;
            const int* sp1 = sp0 + 8 * 512;
            #pragma unroll
            for (int ni = 0; ni < 4; ni++) {
                const int kk = KB + ni * 8 + qc2;
                int2 sd0 = *(const int2*)&sp0[kk];
                int2 sd1 = *(const int2*)&sp1[kk];
                float p0 = __expf(sf[mi][ni][0] + SB2[sd0.x + 1]);
                float p1 = __expf(sf[mi][ni][1] + SB2[sd0.y + 1]);
                float p2 = __expf(sf[mi][ni][2] + SB2[sd1.x + 1]);
                float p3 = __expf(sf[mi][ni][3] + SB2[sd1.y + 1]);
                rsum[mi][0] += p0 + p1;
                rsum[mi][1] += p2 + p3;
                sf[mi][ni][0] = p0; sf[mi][ni][1] = p1;
                sf[mi][ni][2] = p2; sf[mi][ni][3] = p3;
            }
        }

        #pragma unroll
        for (int t = 0; t < 2; t++) {
            uint32_t pa0[2][4], pa1[2][4];
            #pragma unroll
            for (int mi = 0; mi < 2; mi++) {
                float* sA = sf[mi][2 * t];
                float* sB = sf[mi][2 * t + 1];
                pa0[mi][0] = packbf(sA[0], sA[1]);
                pa0[mi][1] = packbf(sA[2], sA[3]);
                pa0[mi][2] = packbf(sB[0], sB[1]);
                pa0[mi][3] = packbf(sB[2], sB[3]);
                pa1[mi][0] = packbf_lo(sA[0], sA[1], pa0[mi][0]);
                pa1[mi][1] = packbf_lo(sA[2], sA[3], pa0[mi][1]);
                pa1[mi][2] = packbf_lo(sB[0], sB[1], pa0[mi][2]);
                pa1[mi][3] = packbf_lo(sB[2], sB[3], pa0[mi][3]);
            }
            uint32_t vb0[4][2], vb1[4][2];
            #pragma unroll
            for (int ni = 0; ni < 4; ni++)
                ldmatrix_x2(vb0[ni], &V0t[(ni * 8 + blr) * VPIT + KB + t * 16 + blc]);
            #pragma unroll
            for (int ni = 0; ni < 4; ni++)
                ldmatrix_x2(vb1[ni], &V1t[(ni * 8 + blr) * VPIT + KB + t * 16 + blc]);
            #pragma unroll
            for (int mi = 0; mi < 2; mi++)
                #pragma unroll
                for (int ni = 0; ni < 4; ni++) {
                    mma_bf16(o[mi][ni], pa0[mi], vb0[ni]);
                    mma_bf16(o[mi][ni], pa1[mi], vb0[ni]);
                    mma_bf16(o[mi][ni], pa0[mi], vb1[ni]);
                }
        }
    }

    #pragma unroll
    for (int mi = 0; mi < 2; mi++) {
        float s0 = rsum[mi][0];
        s0 += __shfl_xor_sync(0xffffffffu, s0, 1);
        s0 += __shfl_xor_sync(0xffffffffu, s0, 2);
        float s1 = rsum[mi][1];
        s1 += __shfl_xor_sync(0xffffffffu, s1, 1);
        s1 += __shfl_xor_sync(0xffffffffu, s1, 2);
        float inv0 = 1.f / s0;
        float inv1 = 1.f / s1;
        const size_t gr0 = (size_t)b * 512 + R + mi * 16 + qr;
        #pragma unroll
        for (int ni = 0; ni < 4; ni++) {
            const int dh = qcol + ni * 8 + qc2;
            float v00 = o[mi][ni][0] * inv0;
            float v01 = o[mi][ni][1] * inv0;
            float v10 = o[mi][ni][2] * inv1;
            float v11 = o[mi][ni][3] * inv1;
            uint32_t hi0 = packbf(v00, v01);
            uint32_t lo0 = packbf_lo(v00, v01, hi0);
            uint32_t hi1 = packbf(v10, v11);
            uint32_t lo1 = packbf_lo(v10, v11, hi1);
            *(uint32_t*)&U0[gr0 * 256 + dh]       = hi0;
            *(uint32_t*)&U1[gr0 * 256 + dh]       = lo0;
            *(uint32_t*)&U0[(gr0 + 8) * 256 + dh] = hi1;
            *(uint32_t*)&U1[(gr0 + 8) * 256 + dh] = lo1;
        }
    }
}

// ---------------------------------------------------------------------------
// Launch. Slot 4 = lin_first gemm128 (ncu window).
// ---------------------------------------------------------------------------
extern "C" void kernel_launch(void* const* d_in, const int* in_sizes, int n_in,
                              void* d_out, int out_size) {
    const float* x       = (const float*)d_in[0];
    const int*   adj     = (const int*)  d_in[1];
    const int*   spd     = (const int*)  d_in[2];
    const float* W_first = (const float*)d_in[3];
    const float* b_first = (const float*)d_in[4];
    const float* bn1_g   = (const float*)d_in[5];
    const float* bn1_b   = (const float*)d_in[6];
    const float* deg_emb = (const float*)d_in[7];
    const float* spd_emb = (const float*)d_in[8];
    const float* Wqkv    = (const float*)d_in[9];
    const float* bqkv    = (const float*)d_in[10];
    const float* Wo      = (const float*)d_in[11];
    const float* bo      = (const float*)d_in[12];
    const float* ln1_g   = (const float*)d_in[13];
    const float* ln1_b   = (const float*)d_in[14];
    const float* W1      = (const float*)d_in[15];
    const float* b1      = (const float*)d_in[16];
    const float* W2      = (const float*)d_in[17];
    const float* b2      = (const float*)d_in[18];
    const float* ln2_g   = (const float*)d_in[19];
    const float* ln2_b   = (const float*)d_in[20];
    const float* W_in    = (const float*)d_in[21];
    const float* b_in    = (const float*)d_in[22];
    const float* bn2_g   = (const float*)d_in[23];
    const float* bn2_b   = (const float*)d_in[24];
    float* out = (float*)d_out;

    float *pH, *pT1;
    __nv_bfloat16 *pH0, *pH1, *pU0, *pU1, *pW0, *pW1, *pS0, *pS1;
    cudaGetSymbolAddress((void**)&pH,  g_h);
    cudaGetSymbolAddress((void**)&pT1, g_t1);
    cudaGetSymbolAddress((void**)&pH0, g_h0);
    cudaGetSymbolAddress((void**)&pH1, g_h1);
    cudaGetSymbolAddress((void**)&pU0, g_u0);
    cudaGetSymbolAddress((void**)&pU1, g_u1);
    cudaGetSymbolAddress((void**)&pW0, g_w0);
    cudaGetSymbolAddress((void**)&pW1, g_w1);
    cudaGetSymbolAddress((void**)&pS0, g_s0);
    cudaGetSymbolAddress((void**)&pS1, g_s1);

    cudaFuncSetAttribute(attn_fa,
                         cudaFuncAttributeMaxDynamicSharedMemorySize, ATTN_SMEM);
    cudaFuncSetAttribute(gemm128<0>,
                         cudaFuncAttributeMaxDynamicSharedMemorySize, G128_SMEM);
    cudaFuncSetAttribute(gemm128<1>,
                         cudaFuncAttributeMaxDynamicSharedMemorySize, G128_SMEM);
    cudaFuncSetAttribute(gemm128<2>,
                         cudaFuncAttributeMaxDynamicSharedMemorySize, G128_SMEM);
    cudaFuncSetAttribute(gemm256_ln,
                         cudaFuncAttributeMaxDynamicSharedMemorySize, G256_SMEM);

    const dim3 g2(128, 2), g6(128, 6), g1(128, 1);

    split_kernel<<<M_ * 64 / 256, 256>>>(x, pH0, pH1, M_ * 64);             // 1
    split5_kernel<<<512, 256>>>(W_first, Wo, W1, W2, W_in, pW0, pW1);       // 2
    deg_kernel<<<dim3(4, 32), 128>>>(adj);                                  // 3
    gemm128<0><<<g2, 256, G128_SMEM>>>(pH0, pH1, pW0 + OFF_FIRST,           // 4
                                       pW1 + OFF_FIRST, b_first, pT1,
                                       nullptr, nullptr, 256);
    split_kernel<<<384, 256>>>(Wqkv, pW0 + OFF_QKV, pW1 + OFF_QKV, 98304);  // 5
    finalize_bn_kernel<<<1, 256>>>(bn1_g, bn1_b);
    bn_deg_kernel<<<M_ * 64 / 256, 256>>>(pT1, deg_emb);

    for (int l = 0; l < L_; l++) {
        gemm128<2><<<g6, 256, G128_SMEM>>>(pH0, pH1,
            pW0 + OFF_QKV + (size_t)l * 196608, pW1 + OFF_QKV + (size_t)l * 196608,
            bqkv + l * 768, nullptr, pS0, pS1, 768);
        attn_fa<<<B_ * H_, 512, ATTN_SMEM>>>(pS0, pS1, spd, spd_emb, pU0, pU1);
        gemm256_ln<<<g1, 256, G256_SMEM>>>(pU0, pU1,
            pW0 + OFF_WO + (size_t)l * 65536, pW1 + OFF_WO + (size_t)l * 65536,
            bo + l * 256, pH, pH0, pH1, ln1_g + l * 256, ln1_b + l * 256);
        gemm128<1><<<g2, 256, G128_SMEM>>>(pH0, pH1,
            pW0 + OFF_W1 + (size_t)l * 65536, pW1 + OFF_W1 + (size_t)l * 65536,
            b1 + l * 256, nullptr, pU0, pU1, 256);
        gemm256_ln<<<g1, 256, G256_SMEM>>>(pU0, pU1,
            pW0 + OFF_W2 + (size_t)l * 65536, pW1 + OFF_W2 + (size_t)l * 65536,
            b2 + l * 256, pH, pH0, pH1, ln2_g + l * 256, ln2_b + l * 256);
    }

    gemm128<0><<<g2, 256, G128_SMEM>>>(pH0, pH1, pW0 + OFF_WIN, pW1 + OFF_WIN,
                                       b_in, pT1, nullptr, nullptr, 256);
    finalize_bn_kernel<<<1, 256>>>(bn2_g, bn2_b);
    bn_out_kernel<<<M_ * 64 / 256, 256>>>(pT1, out);
}